// round 12
// baseline (speedup 1.0000x reference)
#include <cuda_runtime.h>

typedef unsigned long long ull_t;

// ---------------- scratch (static device globals; no allocation) ------------
__device__ float g_preact[9633792];   // max partial store: L1 2*16*112*112*24
__device__ float g_act[2408448];      // max pooled/layer-input: 2*16*56*56*24
__device__ float g_wf[1990656];       // max fused weight: 5184*384
__device__ float g_sum[384];
__device__ float g_sumsq[384];
__device__ float g_scale[384];
__device__ float g_shift[384];
__device__ float g_fc1[1024];
__device__ float g_fc2[512];

#define PACK2(d, s) asm("mov.b64 %0, {%1, %1};" : "=l"(d) : "f"(s))
#define FMA2(d, a, b) asm("fma.rn.f32x2 %0, %1, %2, %0;" : "+l"(d) : "l"(a), "l"(b))

// ---------------- input transpose: (2,3,16,112,112) -> (2,16,112,112,3) -----
__global__ void nchw2nhwc_kernel(const float* __restrict__ x, float* __restrict__ out,
                                 float* __restrict__ sum, float* __restrict__ sq) {
    const int DHW = 16 * 112 * 112;
    const int N = 2 * DHW * 3;
    int e = blockIdx.x * blockDim.x + threadIdx.x;
    if (e < 384) { sum[e] = 0.f; sq[e] = 0.f; }   // upfront stats zero
    if (e >= N) return;
    int c = e % 3;
    int m = e / 3;
    int b = m / DHW;
    int r = m - b * DHW;
    out[e] = x[(b * 3 + c) * DHW + r];
}

// ---------------- small fused-weight GEMM (layers 1-2) ----------------------
// Wf[s*C+c][o] = sum_p proj[p][c*27+s] * alpha[p][o]
template <int BN, int TN>
__global__ void fusew_kernel(const float* __restrict__ proj, const float* __restrict__ alpha,
                             float* __restrict__ Wf, int K, int C, int O) {
    constexpr int BM = 64, KC = 16;
    __shared__ alignas(16) float As[KC][BM];
    __shared__ alignas(16) float Bs[KC][BN];
    const int m0 = blockIdx.x * BM;
    const int n0 = blockIdx.y * BN;
    const int tid = threadIdx.x;
    const int tm = tid >> 4;
    const int tn = tid & 15;

    float acc[4][TN];
#pragma unroll
    for (int i = 0; i < 4; i++)
#pragma unroll
        for (int j = 0; j < TN; j++) acc[i][j] = 0.f;

    for (int p0 = 0; p0 < 512; p0 += KC) {
        __syncthreads();
        for (int idx = tid; idx < KC * BM; idx += 256) {
            int pp = idx / BM, i = idx - pp * BM;
            int m = m0 + i;
            As[pp][i] = (m < K) ? proj[(p0 + pp) * K + m] : 0.f;
        }
        for (int idx = tid; idx < KC * BN; idx += 256) {
            int pp = idx / BN, j = idx - pp * BN;
            int n = n0 + j;
            Bs[pp][j] = (n < O) ? alpha[(p0 + pp) * O + n] : 0.f;
        }
        __syncthreads();
#pragma unroll
        for (int pp = 0; pp < KC; ++pp) {
            float4 a4 = *(const float4*)&As[pp][tm * 4];
            float av[4] = {a4.x, a4.y, a4.z, a4.w};
            float bv[TN];
            if constexpr (TN == 4) {
                float4 b4 = *(const float4*)&Bs[pp][tn * 4];
                bv[0] = b4.x; bv[1] = b4.y; bv[2] = b4.z; bv[3] = b4.w;
            } else {
                float2 b2 = *(const float2*)&Bs[pp][tn * 2];
                bv[0] = b2.x; bv[1] = b2.y;
            }
#pragma unroll
            for (int mm = 0; mm < 4; ++mm)
#pragma unroll
                for (int nn = 0; nn < TN; ++nn)
                    acc[mm][nn] = fmaf(av[mm], bv[nn], acc[mm][nn]);
        }
    }
#pragma unroll
    for (int mm = 0; mm < 4; ++mm) {
        int m = m0 + tm * 4 + mm;
        if (m < K) {
            int c = m / 27;
            int s = m - c * 27;
            float* dst = Wf + (s * C + c) * O + n0 + tn * TN;
#pragma unroll
            for (int nn = 0; nn < TN; ++nn) {
                int n = n0 + tn * TN + nn;
                if (n < O) dst[nn] = acc[mm][nn];
            }
        }
    }
}

// ---------------- big fused-weight GEMM (layers 3-5), FFMA2 + double buffer --
// Latency-coverage config: 384 threads/block (12 warps, 3/SMSP), TM=4, same
// BM128/BN96 tiles and grids as the best-measured layout.
template <int BM, int BN, int TM, int TN, int KC, int THREADS>
__global__ void __launch_bounds__(THREADS, 1)
fusew2_kernel(const float* __restrict__ proj, const float* __restrict__ alpha,
              float* __restrict__ Wf, int K, int C, int O) {
    constexpr int NCOL = BN / TN;
    constexpr int TNH = TN / 2;
    constexpr int NCHUNK = 512 / KC;
    constexpr int A4 = BM * KC / 4;
    constexpr int NA = (A4 + THREADS - 1) / THREADS;
    constexpr int B4 = BN * KC / 4;
    constexpr int NB = (B4 + THREADS - 1) / THREADS;
    __shared__ alignas(16) float As[2][KC][BM];
    __shared__ alignas(16) float Bs[2][KC][BN];
    const int m0 = blockIdx.x * BM;
    const int n0 = blockIdx.y * BN;
    const int tid = threadIdx.x;
    const int col = tid % NCOL, row = tid / NCOL;
    const int rowBase = row * TM, colBase = col * TN;

    ull_t acc[TM][TNH];
#pragma unroll
    for (int a = 0; a < TM; a++)
#pragma unroll
        for (int b = 0; b < TNH; b++) acc[a][b] = 0ULL;

    float4 stA[NA], stB[NB];
    auto gather = [&](int j) {
        int p0 = j * KC;
#pragma unroll
        for (int t = 0; t < NA; t++) {
            int q = tid + t * THREADS;
            float4 v = make_float4(0.f, 0.f, 0.f, 0.f);
            if (A4 % THREADS == 0 || q < A4) {
                int i4 = q % (BM / 4);
                int pp = q / (BM / 4);
                int m = m0 + i4 * 4;
                if (m < K) v = *reinterpret_cast<const float4*>(proj + (size_t)(p0 + pp) * K + m);
            }
            stA[t] = v;
        }
#pragma unroll
        for (int t = 0; t < NB; t++) {
            int q = tid + t * THREADS;
            float4 v = make_float4(0.f, 0.f, 0.f, 0.f);
            if (B4 % THREADS == 0 || q < B4) {
                int cc = q / (BN / 4);
                int c4 = q % (BN / 4);
                v = *reinterpret_cast<const float4*>(alpha + (size_t)(p0 + cc) * O + n0 + c4 * 4);
            }
            stB[t] = v;
        }
    };
    auto commit = [&](int buf) {
#pragma unroll
        for (int t = 0; t < NA; t++) {
            int q = tid + t * THREADS;
            if (A4 % THREADS == 0 || q < A4) {
                int i4 = q % (BM / 4);
                int pp = q / (BM / 4);
                *reinterpret_cast<float4*>(&As[buf][pp][i4 * 4]) = stA[t];
            }
        }
#pragma unroll
        for (int t = 0; t < NB; t++) {
            int q = tid + t * THREADS;
            if (B4 % THREADS == 0 || q < B4) {
                int cc = q / (BN / 4);
                int c4 = q % (BN / 4);
                *reinterpret_cast<float4*>(&Bs[buf][cc][c4 * 4]) = stB[t];
            }
        }
    };

    gather(0);
    commit(0);
    __syncthreads();
    int cur = 0;
    for (int j = 0; j < NCHUNK; ++j) {
        if (j + 1 < NCHUNK) gather(j + 1);
#pragma unroll
        for (int cc = 0; cc < KC; ++cc) {
            float a[TM];
#pragma unroll
            for (int f = 0; f < TM; f += 4)
                *reinterpret_cast<float4*>(&a[f]) =
                    *reinterpret_cast<const float4*>(&As[cur][cc][rowBase + f]);
            ull_t bp[TNH];
            ulonglong2 b0 = *reinterpret_cast<const ulonglong2*>(&Bs[cur][cc][colBase]);
            ulonglong2 b1 = *reinterpret_cast<const ulonglong2*>(&Bs[cur][cc][colBase + 4]);
            bp[0] = b0.x; bp[1] = b0.y; bp[2] = b1.x; bp[3] = b1.y;
#pragma unroll
            for (int mm = 0; mm < TM; mm++) {
                ull_t ap;
                PACK2(ap, a[mm]);
#pragma unroll
                for (int p = 0; p < TNH; p++) FMA2(acc[mm][p], ap, bp[p]);
            }
        }
        if (j + 1 < NCHUNK) commit(cur ^ 1);
        __syncthreads();
        cur ^= 1;
    }

#pragma unroll
    for (int mm = 0; mm < TM; mm++) {
        int m = m0 + rowBase + mm;
        if (m < K) {
            int c = m / 27;
            int s = m - c * 27;
            ull_t* dst = reinterpret_cast<ull_t*>(Wf + ((size_t)(s * C + c)) * O + n0 + colBase);
#pragma unroll
            for (int p = 0; p < TNH; p++) dst[p] = acc[mm][p];
        }
    }
}

// ---------------- layer-1 direct conv (C=3, O=24), writes RAW sums ----------
__global__ void conv1_kernel(const float* __restrict__ X, const float* __restrict__ Wf,
                             float* __restrict__ Y) {
    __shared__ alignas(16) float sW[81 * 24];
    for (int i = threadIdx.x; i < 81 * 24; i += 256) sW[i] = Wf[i];
    __syncthreads();
    int m = blockIdx.x * 256 + threadIdx.x;  // M = 401408 exact
    int w = m % 112;
    int t = m / 112;
    int h = t % 112;
    t /= 112;
    int d = t % 16;
    ull_t acc[12];
#pragma unroll
    for (int p = 0; p < 12; p++) acc[p] = 0ULL;
    const float* base = X + (size_t)m * 3;
#pragma unroll
    for (int s = 0; s < 27; s++) {
        const int dz = s / 9 - 1, dy = (s / 3) % 3 - 1, dx = s % 3 - 1;
        int dd = d + dz, hh = h + dy, ww = w + dx;
        float x0 = 0.f, x1 = 0.f, x2 = 0.f;
        if ((unsigned)dd < 16u && (unsigned)hh < 112u && (unsigned)ww < 112u) {
            const float* px = base + ((dz * 112 + dy) * 112 + dx) * 3;
            x0 = px[0]; x1 = px[1]; x2 = px[2];
        }
        float xv[3] = {x0, x1, x2};
#pragma unroll
        for (int c = 0; c < 3; c++) {
            ull_t xp;
            PACK2(xp, xv[c]);
            const ulonglong2* wr = reinterpret_cast<const ulonglong2*>(&sW[(s * 3 + c) * 24]);
#pragma unroll
            for (int p2 = 0; p2 < 6; p2++) {
                ulonglong2 wv = wr[p2];
                FMA2(acc[2 * p2], xp, wv.x);
                FMA2(acc[2 * p2 + 1], xp, wv.y);
            }
        }
    }
    ull_t* dst = reinterpret_cast<ull_t*>(Y + (size_t)m * 24);
#pragma unroll
    for (int p = 0; p < 12; p++) dst[p] = acc[p];
}

// ---------------- implicit-GEMM conv: FFMA2, double buffer, split-K ----------
// BN of the PREVIOUS layer fused into the A-gather (x*scale[c]+shift[c],
// zeros stay zero for padding — matches reference BN-then-pad order).
// X: [B,D,H,W,C], Wf: [27*C][O] (row = s*C+c), Yp: S partial slices (RAW sums)
template <int BM, int BN, int TM, int TN, int KC, int C, int THREADS, bool BNIN>
__global__ void __launch_bounds__(THREADS, 2)
conv2_kernel(const float* __restrict__ X, const float* __restrict__ Wf,
             float* __restrict__ Yp, const float* __restrict__ scl,
             const float* __restrict__ shf,
             int B_, int D, int H, int W, int O, int S) {
    constexpr int NCOL = BN / TN;
    constexpr int CPT = C / KC;
    constexpr int TNH = TN / 2;
    constexpr int A4 = BM * KC / 4;
    constexpr int NA = (A4 + THREADS - 1) / THREADS;
    constexpr int B4 = BN * KC / 4;
    constexpr int NB = (B4 + THREADS - 1) / THREADS;
    __shared__ alignas(16) float As[2][KC][BM];
    __shared__ alignas(16) float Bs[2][KC][BN];
    __shared__ int sBase[BM];
    __shared__ int sDHW[BM];
    __shared__ alignas(16) float sScale[BNIN ? C : 4];
    __shared__ alignas(16) float sShift[BNIN ? C : 4];
    const int M = B_ * D * H * W;
    const int m0 = blockIdx.x * BM;
    const int n0 = blockIdx.y * BN;
    const int z = blockIdx.z;
    const int s0 = (27 * z) / S, s1 = (27 * (z + 1)) / S;
    const int nChunks = (s1 - s0) * CPT;
    const int tid = threadIdx.x;
    const int col = tid % NCOL, row = tid / NCOL;
    const int rowBase = row * TM, colBase = col * TN;

    if constexpr (BNIN) {
        for (int i = tid; i < C; i += THREADS) {
            sScale[i] = scl[i];
            sShift[i] = shf[i];
        }
    }
    for (int i = tid; i < BM; i += THREADS) {
        int m = m0 + i;
        if (m < M) {
            int w = m % W;
            int t = m / W;
            int h = t % H;
            t /= H;
            int d = t % D;
            sBase[i] = m * C;
            sDHW[i] = (d << 20) | (h << 10) | w;
        } else {
            sBase[i] = -1;
            sDHW[i] = 0;
        }
    }
    __syncthreads();

    ull_t acc[TM][TNH];
#pragma unroll
    for (int a = 0; a < TM; a++)
#pragma unroll
        for (int b = 0; b < TNH; b++) acc[a][b] = 0ULL;

    float4 stA[NA], stB[NB];
    auto gather = [&](int j) {
        int s = s0 + j / CPT;
        int c0 = (j % CPT) * KC;
        int dz = s / 9 - 1, dy = (s / 3) % 3 - 1, dx = s % 3 - 1;
        int koff = ((dz * H + dy) * W + dx) * C + c0;
#pragma unroll
        for (int t = 0; t < NA; t++) {
            int q = tid + t * THREADS;
            float4 v = make_float4(0.f, 0.f, 0.f, 0.f);
            if (A4 % THREADS == 0 || q < A4) {
                int i = q % BM;
                int cc4 = q / BM;
                int bs = sBase[i];
                if (bs >= 0) {
                    int dhw = sDHW[i];
                    int dd = (dhw >> 20) + dz;
                    int hh = ((dhw >> 10) & 1023) + dy;
                    int ww = (dhw & 1023) + dx;
                    if ((unsigned)dd < (unsigned)D && (unsigned)hh < (unsigned)H &&
                        (unsigned)ww < (unsigned)W) {
                        v = *reinterpret_cast<const float4*>(X + bs + koff + cc4 * 4);
                        if constexpr (BNIN) {
                            int ch = c0 + cc4 * 4;
                            float4 sc = *reinterpret_cast<const float4*>(&sScale[ch]);
                            float4 sh = *reinterpret_cast<const float4*>(&sShift[ch]);
                            v.x = fmaf(v.x, sc.x, sh.x);
                            v.y = fmaf(v.y, sc.y, sh.y);
                            v.z = fmaf(v.z, sc.z, sh.z);
                            v.w = fmaf(v.w, sc.w, sh.w);
                        }
                    }
                }
            }
            stA[t] = v;
        }
        const float* wb = Wf + ((size_t)(s * C + c0)) * O + n0;
#pragma unroll
        for (int t = 0; t < NB; t++) {
            int q = tid + t * THREADS;
            float4 v = make_float4(0.f, 0.f, 0.f, 0.f);
            if (B4 % THREADS == 0 || q < B4) {
                int cc = q / (BN / 4);
                int c4 = q % (BN / 4);
                v = *reinterpret_cast<const float4*>(wb + (size_t)cc * O + c4 * 4);
            }
            stB[t] = v;
        }
    };
    auto commit = [&](int buf) {
#pragma unroll
        for (int t = 0; t < NA; t++) {
            int q = tid + t * THREADS;
            if (A4 % THREADS == 0 || q < A4) {
                int i = q % BM;
                int cc = (q / BM) * 4;
                As[buf][cc + 0][i] = stA[t].x;
                As[buf][cc + 1][i] = stA[t].y;
                As[buf][cc + 2][i] = stA[t].z;
                As[buf][cc + 3][i] = stA[t].w;
            }
        }
#pragma unroll
        for (int t = 0; t < NB; t++) {
            int q = tid + t * THREADS;
            if (B4 % THREADS == 0 || q < B4) {
                int cc = q / (BN / 4);
                int c4 = q % (BN / 4);
                *reinterpret_cast<float4*>(&Bs[buf][cc][c4 * 4]) = stB[t];
            }
        }
    };

    gather(0);
    commit(0);
    __syncthreads();
    int cur = 0;
    for (int j = 0; j < nChunks; ++j) {
        if (j + 1 < nChunks) gather(j + 1);
#pragma unroll
        for (int cc = 0; cc < KC; ++cc) {
            float a[TM];
            *reinterpret_cast<float4*>(&a[0]) = *reinterpret_cast<const float4*>(&As[cur][cc][rowBase]);
            *reinterpret_cast<float4*>(&a[4]) = *reinterpret_cast<const float4*>(&As[cur][cc][rowBase + 4]);
            ull_t bp[TNH];
            if constexpr (TN == 8) {
                ulonglong2 b0 = *reinterpret_cast<const ulonglong2*>(&Bs[cur][cc][colBase]);
                ulonglong2 b1 = *reinterpret_cast<const ulonglong2*>(&Bs[cur][cc][colBase + 4]);
                bp[0] = b0.x; bp[1] = b0.y; bp[2] = b1.x; bp[3] = b1.y;
            } else {
                const ull_t* pb = reinterpret_cast<const ull_t*>(&Bs[cur][cc][colBase]);
#pragma unroll
                for (int p = 0; p < TNH; p++) bp[p] = pb[p];
            }
#pragma unroll
            for (int mm = 0; mm < TM; mm++) {
                ull_t ap;
                PACK2(ap, a[mm]);
#pragma unroll
                for (int p = 0; p < TNH; p++) FMA2(acc[mm][p], ap, bp[p]);
            }
        }
        if (j + 1 < nChunks) commit(cur ^ 1);
        __syncthreads();
        cur ^= 1;
    }

    float* out = Yp + (size_t)z * M * O;
#pragma unroll
    for (int mm = 0; mm < TM; mm++) {
        int m = m0 + rowBase + mm;
        if (m < M) {
            ull_t* dst = reinterpret_cast<ull_t*>(out + (size_t)m * O + n0 + colBase);
#pragma unroll
            for (int p = 0; p < TNH; p++) dst[p] = acc[mm][p];
        }
    }
}

// ------ split-K reduce + clamp(1+x,0) + maxpool (1,2,2) + sum/sumsq ----------
// float4 over channels; grid chosen so stride % (O/4) == 0 -> each thread's
// channel group is FIXED, so stats accumulate in registers; 8 shared atomics
// per thread total. Writes PRE-BN pooled activations.
__global__ void pool_stats_kernel(const float* __restrict__ Y, float* __restrict__ P,
                                  float* __restrict__ gsum, float* __restrict__ gsq,
                                  int B, int D, int H, int W, int O, int Hp, int Wp,
                                  int S, int sliceStride) {
    __shared__ float ssum[384];
    __shared__ float ssq[384];
    int tid = threadIdx.x;
    for (int o = tid; o < O; o += blockDim.x) { ssum[o] = 0.f; ssq[o] = 0.f; }
    __syncthreads();
    const int O4 = O >> 2;
    const int Ne4 = B * D * Hp * Wp * O4;
    const int stride = gridDim.x * blockDim.x;   // launch guarantees stride % O4 == 0
    const int e0 = blockIdx.x * blockDim.x + tid;
    const int c4 = e0 % O4;                      // constant across the loop
    float4 rs = make_float4(0.f, 0.f, 0.f, 0.f);
    float4 rq = make_float4(0.f, 0.f, 0.f, 0.f);
    for (int e = e0; e < Ne4; e += stride) {
        int m = e / O4;
        int wp = m % Wp;
        int t = m / Wp;
        int hp = t % Hp;
        t /= Hp;
        int d = t % D;
        int b = t / D;
        const float* src = Y + ((size_t)(((b * D + d) * H + hp * 2) * W) + wp * 2) * O + c4 * 4;
        float4 v0 = *reinterpret_cast<const float4*>(src);
        float4 v1 = *reinterpret_cast<const float4*>(src + O);
        float4 v2 = *reinterpret_cast<const float4*>(src + (size_t)W * O);
        float4 v3 = *reinterpret_cast<const float4*>(src + (size_t)W * O + O);
        for (int s = 1; s < S; s++) {
            const float* s2 = src + (size_t)s * sliceStride;
            float4 u0 = *reinterpret_cast<const float4*>(s2);
            float4 u1 = *reinterpret_cast<const float4*>(s2 + O);
            float4 u2 = *reinterpret_cast<const float4*>(s2 + (size_t)W * O);
            float4 u3 = *reinterpret_cast<const float4*>(s2 + (size_t)W * O + O);
            v0.x += u0.x; v0.y += u0.y; v0.z += u0.z; v0.w += u0.w;
            v1.x += u1.x; v1.y += u1.y; v1.z += u1.z; v1.w += u1.w;
            v2.x += u2.x; v2.y += u2.y; v2.z += u2.z; v2.w += u2.w;
            v3.x += u3.x; v3.y += u3.y; v3.z += u3.z; v3.w += u3.w;
        }
        float4 v;
        v.x = fmaxf(1.f + fmaxf(fmaxf(v0.x, v1.x), fmaxf(v2.x, v3.x)), 0.f);
        v.y = fmaxf(1.f + fmaxf(fmaxf(v0.y, v1.y), fmaxf(v2.y, v3.y)), 0.f);
        v.z = fmaxf(1.f + fmaxf(fmaxf(v0.z, v1.z), fmaxf(v2.z, v3.z)), 0.f);
        v.w = fmaxf(1.f + fmaxf(fmaxf(v0.w, v1.w), fmaxf(v2.w, v3.w)), 0.f);
        *reinterpret_cast<float4*>(P + (size_t)m * O + c4 * 4) = v;
        rs.x += v.x; rs.y += v.y; rs.z += v.z; rs.w += v.w;
        rq.x += v.x * v.x; rq.y += v.y * v.y; rq.z += v.z * v.z; rq.w += v.w * v.w;
    }
    atomicAdd(&ssum[c4 * 4 + 0], rs.x);
    atomicAdd(&ssum[c4 * 4 + 1], rs.y);
    atomicAdd(&ssum[c4 * 4 + 2], rs.z);
    atomicAdd(&ssum[c4 * 4 + 3], rs.w);
    atomicAdd(&ssq[c4 * 4 + 0], rq.x);
    atomicAdd(&ssq[c4 * 4 + 1], rq.y);
    atomicAdd(&ssq[c4 * 4 + 2], rq.z);
    atomicAdd(&ssq[c4 * 4 + 3], rq.w);
    __syncthreads();
    for (int o = tid; o < O; o += blockDim.x) {
        atomicAdd(&gsum[o], ssum[o]);
        atomicAdd(&gsq[o], ssq[o]);
    }
}

// Computes scale/shift, then RE-ZEROES the stat buffers for the next layer
// (stream-ordered before the next pool; deterministic across graph replays).
__global__ void bn_final_kernel(float* __restrict__ sum, float* __restrict__ sq,
                                const float* __restrict__ gamma, const float* __restrict__ beta,
                                float* __restrict__ scale, float* __restrict__ shift,
                                float invN, int O) {
    int o = threadIdx.x;
    if (o < O) {
        float mean = sum[o] * invN;
        float var = sq[o] * invN - mean * mean;
        float sc = gamma[o] * rsqrtf(var + 1e-5f);
        scale[o] = sc;
        shift[o] = beta[o] - mean * sc;
    }
    if (o < 384) { sum[o] = 0.f; sq[o] = 0.f; }
}

// ---------------- FC layers --------------------------------------------------
// v: pooled L5 (pre-BN); BN affine applied inline here.
__global__ void fc1_kernel(const float* __restrict__ v, const float* __restrict__ w1,
                           const float* __restrict__ b1,
                           const float* __restrict__ scale, const float* __restrict__ shift,
                           float* __restrict__ out) {
    __shared__ float s0[256];
    __shared__ float s1[256];
    __shared__ float sSc[384];
    __shared__ float sSh[384];
    int j = blockIdx.x;
    int tid = threadIdx.x;
    for (int o = tid; o < 384; o += 256) { sSc[o] = scale[o]; sSh[o] = shift[o]; }
    __syncthreads();
    const float* wr = w1 + (size_t)j * 55296;
    float a0 = 0.f, a1 = 0.f;
    for (int k = tid; k < 55296; k += 256) {
        int o = k / 144;
        int r = k - o * 144;
        int idx = r * 384 + o;
        float sc = sSc[o], sh = sSh[o];
        float wv = wr[k];
        a0 += wv * fmaf(v[idx], sc, sh);
        a1 += wv * fmaf(v[idx + 55296], sc, sh);
    }
    s0[tid] = a0; s1[tid] = a1;
    __syncthreads();
    for (int t = 128; t > 0; t >>= 1) {
        if (tid < t) { s0[tid] += s0[tid + t]; s1[tid] += s1[tid + t]; }
        __syncthreads();
    }
    if (tid == 0) {
        out[j] = fmaxf(s0[0] + b1[j], 0.f);
        out[512 + j] = fmaxf(s1[0] + b1[j], 0.f);
    }
}

__global__ void fc2_kernel(const float* __restrict__ in, const float* __restrict__ w2,
                           const float* __restrict__ b2, float* __restrict__ out) {
    __shared__ float s0[128];
    __shared__ float s1[128];
    int i = blockIdx.x;
    int tid = threadIdx.x;
    float a0 = 0.f, a1 = 0.f;
    for (int j = tid; j < 512; j += 128) {
        float wv = w2[i * 512 + j];
        a0 += wv * in[j];
        a1 += wv * in[512 + j];
    }
    s0[tid] = a0; s1[tid] = a1;
    __syncthreads();
    for (int t = 64; t > 0; t >>= 1) {
        if (tid < t) { s0[tid] += s0[tid + t]; s1[tid] += s1[tid + t]; }
        __syncthreads();
    }
    if (tid == 0) {
        out[i] = fmaxf(s0[0] + b2[i], 0.f);
        out[256 + i] = fmaxf(s1[0] + b2[i], 0.f);
    }
}

__global__ void fc3_kernel(const float* __restrict__ in, const float* __restrict__ w3,
                           const float* __restrict__ b3, float* __restrict__ out) {
    __shared__ float s0[128];
    __shared__ float s1[128];
    int i = blockIdx.x;
    int tid = threadIdx.x;
    float a0 = 0.f, a1 = 0.f;
    for (int j = tid; j < 256; j += 128) {
        float wv = w3[i * 256 + j];
        a0 += wv * in[j];
        a1 += wv * in[256 + j];
    }
    s0[tid] = a0; s1[tid] = a1;
    __syncthreads();
    for (int t = 64; t > 0; t >>= 1) {
        if (tid < t) { s0[tid] += s0[tid + t]; s1[tid] += s1[tid + t]; }
        __syncthreads();
    }
    if (tid == 0) {
        out[i] = s0[0] + b3[i];
        out[101 + i] = s1[0] + b3[i];
    }
}

// ---------------- driver ------------------------------------------------------
extern "C" void kernel_launch(void* const* d_in, const int* in_sizes, int n_in,
                              void* d_out, int out_size) {
    const float* x = (const float*)d_in[0];
    const float* Pj[5];
    const float* Al[5];
    const float* Ga[5];
    const float* Be[5];
    for (int i = 0; i < 5; i++) {
        Pj[i] = (const float*)d_in[1 + 4 * i];
        Al[i] = (const float*)d_in[2 + 4 * i];
        Ga[i] = (const float*)d_in[3 + 4 * i];
        Be[i] = (const float*)d_in[4 + 4 * i];
    }
    const float* w1 = (const float*)d_in[21];
    const float* b1 = (const float*)d_in[22];
    const float* w2 = (const float*)d_in[23];
    const float* b2 = (const float*)d_in[24];
    const float* w3 = (const float*)d_in[25];
    const float* b3 = (const float*)d_in[26];

    float *preact, *act, *wf, *sum, *sq, *scale, *shift, *fc1b, *fc2b;
    cudaGetSymbolAddress((void**)&preact, g_preact);
    cudaGetSymbolAddress((void**)&act, g_act);
    cudaGetSymbolAddress((void**)&wf, g_wf);
    cudaGetSymbolAddress((void**)&sum, g_sum);
    cudaGetSymbolAddress((void**)&sq, g_sumsq);
    cudaGetSymbolAddress((void**)&scale, g_scale);
    cudaGetSymbolAddress((void**)&shift, g_shift);
    cudaGetSymbolAddress((void**)&fc1b, g_fc1);
    cudaGetSymbolAddress((void**)&fc2b, g_fc2);

    // input transpose to channel-last (+ upfront stats zero)
    {
        int N = 2 * 3 * 16 * 112 * 112;
        nchw2nhwc_kernel<<<(N + 255) / 256, 256>>>(x, act, sum, sq);
    }

    const int B = 2, D = 16;

    auto do_pool_bn = [&](int C_H, int C_W, int C_O, int C_S, int C_M,
                          const float* gamma, const float* beta) {
        int hp = (C_H - 2) / 2 + 1;
        int wp = (C_W - 2) / 2 + 1;
        int ne4 = B * D * hp * wp * (C_O / 4);
        int pb = (ne4 + 255) / 256;
        pb = ((pb + 2) / 3) * 3;          // multiple of 3 -> stride % (O/4) == 0
        if (pb > 3072) pb = 3072;
        pool_stats_kernel<<<pb, 256>>>(preact, act, sum, sq, B, D, C_H, C_W, C_O, hp, wp,
                                       C_S, C_M * C_O);
        float invN = 1.f / (float)(B * D * hp * wp);
        bn_final_kernel<<<1, 384>>>(sum, sq, gamma, beta, scale, shift, invN, C_O);
    };

    // ---------------- layer 1: C=3, O=24, H=W=112 (no BN on input) ----------
    fusew_kernel<32, 2><<<dim3(2, 1), 256>>>(Pj[0], Al[0], wf, 81, 3, 24);
    conv1_kernel<<<1568, 256>>>(act, wf, preact);
    do_pool_bn(112, 112, 24, 1, 2 * 16 * 112 * 112, Ga[0], Be[0]);

    // ---------------- layer 2: C=24, O=48, H=W=56 ---------------------------
    fusew_kernel<64, 4><<<dim3((648 + 63) / 64, 1), 256>>>(Pj[1], Al[1], wf, 648, 24, 48);
    int M = 2 * 16 * 56 * 56;
    conv2_kernel<128, 48, 8, 6, 8, 24, 128, true>
        <<<dim3(M / 128, 1, 1), 128>>>(act, wf, preact, scale, shift, B, D, 56, 56, 48, 1);
    do_pool_bn(56, 56, 48, 1, M, Ga[1], Be[1]);

    // ---------------- layer 3: C=48, O=96, H=W=28, split-K=3 ----------------
    fusew2_kernel<128, 96, 4, 8, 16, 384>
        <<<dim3(11, 1), 384>>>(Pj[2], Al[2], wf, 1296, 48, 96);
    M = 2 * 16 * 28 * 28;
    conv2_kernel<128, 96, 8, 8, 16, 48, 192, true>
        <<<dim3(M / 128, 1, 3), 192>>>(act, wf, preact, scale, shift, B, D, 28, 28, 96, 3);
    do_pool_bn(28, 28, 96, 3, M, Ga[2], Be[2]);

    // ---------------- layer 4: C=96, O=192, H=W=14, split-K=3 ---------------
    fusew2_kernel<128, 96, 4, 8, 16, 384>
        <<<dim3(21, 2), 384>>>(Pj[3], Al[3], wf, 2592, 96, 192);
    M = 2 * 16 * 14 * 14;
    conv2_kernel<128, 96, 8, 8, 16, 96, 192, true>
        <<<dim3(M / 128, 2, 3), 192>>>(act, wf, preact, scale, shift, B, D, 14, 14, 192, 3);
    do_pool_bn(14, 14, 192, 3, M, Ga[3], Be[3]);

    // ---------------- layer 5: C=192, O=384, H=W=7, split-K=3 (one wave) ----
    fusew2_kernel<128, 96, 4, 8, 16, 384>
        <<<dim3(41, 4), 384>>>(Pj[4], Al[4], wf, 5184, 192, 384);
    M = 2 * 16 * 7 * 7;
    conv2_kernel<64, 128, 8, 8, 16, 192, 128, true>
        <<<dim3((M + 63) / 64, 3, 3), 128>>>(act, wf, preact, scale, shift, B, D, 7, 7, 384, 3);
    do_pool_bn(7, 7, 384, 3, M, Ga[4], Be[4]);

    // ---------------- FC head (L5 BN fused into FC1 input) ------------------
    fc1_kernel<<<512, 256>>>(act, w1, b1, scale, shift, fc1b);
    fc2_kernel<<<256, 128>>>(fc1b, w2, b2, fc2b);
    fc3_kernel<<<101, 128>>>(fc2b, w3, b3, (float*)d_out);
}

// round 13
// speedup vs baseline: 1.0854x; 1.0854x over previous
#include <cuda_runtime.h>

typedef unsigned long long ull_t;

// ---------------- scratch (static device globals; no allocation) ------------
__device__ float g_preact[9633792];   // max partial store: L1 2*16*112*112*24
__device__ float g_act[2408448];      // max pooled/layer-input: 2*16*56*56*24
__device__ float g_wf1[1944];         // 81*24
__device__ float g_wf2[31104];        // 648*48
__device__ float g_wf3[124416];       // 1296*96
__device__ float g_wf4[497664];       // 2592*192
__device__ float g_wf5[1990656];      // 5184*384
__device__ float g_sum[384];
__device__ float g_sumsq[384];
__device__ float g_scale[384];
__device__ float g_shift[384];
__device__ float g_fc1[1024];
__device__ float g_fc2[512];

#define PACK2(d, s) asm("mov.b64 %0, {%1, %1};" : "=l"(d) : "f"(s))
#define FMA2(d, a, b) asm("fma.rn.f32x2 %0, %1, %2, %0;" : "+l"(d) : "l"(a), "l"(b))

// ---------------- input transpose: (2,3,16,112,112) -> (2,16,112,112,3) -----
__global__ void nchw2nhwc_kernel(const float* __restrict__ x, float* __restrict__ out,
                                 float* __restrict__ sum, float* __restrict__ sq) {
    const int DHW = 16 * 112 * 112;
    const int N = 2 * DHW * 3;
    int e = blockIdx.x * blockDim.x + threadIdx.x;
    if (e < 384) { sum[e] = 0.f; sq[e] = 0.f; }   // upfront stats zero
    if (e >= N) return;
    int c = e % 3;
    int m = e / 3;
    int b = m / DHW;
    int r = m - b * DHW;
    out[e] = x[(b * 3 + c) * DHW + r];
}

// ---------------- small fused-weight GEMM (layers 1-2) ----------------------
// Wf[s*C+c][o] = sum_p proj[p][c*27+s] * alpha[p][o]
template <int BN, int TN>
__global__ void fusew_kernel(const float* __restrict__ proj, const float* __restrict__ alpha,
                             float* __restrict__ Wf, int K, int C, int O) {
    constexpr int BM = 64, KC = 16;
    __shared__ alignas(16) float As[KC][BM];
    __shared__ alignas(16) float Bs[KC][BN];
    const int m0 = blockIdx.x * BM;
    const int n0 = blockIdx.y * BN;
    const int tid = threadIdx.x;
    const int tm = tid >> 4;
    const int tn = tid & 15;

    float acc[4][TN];
#pragma unroll
    for (int i = 0; i < 4; i++)
#pragma unroll
        for (int j = 0; j < TN; j++) acc[i][j] = 0.f;

    for (int p0 = 0; p0 < 512; p0 += KC) {
        __syncthreads();
        for (int idx = tid; idx < KC * BM; idx += 256) {
            int pp = idx / BM, i = idx - pp * BM;
            int m = m0 + i;
            As[pp][i] = (m < K) ? proj[(p0 + pp) * K + m] : 0.f;
        }
        for (int idx = tid; idx < KC * BN; idx += 256) {
            int pp = idx / BN, j = idx - pp * BN;
            int n = n0 + j;
            Bs[pp][j] = (n < O) ? alpha[(p0 + pp) * O + n] : 0.f;
        }
        __syncthreads();
#pragma unroll
        for (int pp = 0; pp < KC; ++pp) {
            float4 a4 = *(const float4*)&As[pp][tm * 4];
            float av[4] = {a4.x, a4.y, a4.z, a4.w};
            float bv[TN];
            if constexpr (TN == 4) {
                float4 b4 = *(const float4*)&Bs[pp][tn * 4];
                bv[0] = b4.x; bv[1] = b4.y; bv[2] = b4.z; bv[3] = b4.w;
            } else {
                float2 b2 = *(const float2*)&Bs[pp][tn * 2];
                bv[0] = b2.x; bv[1] = b2.y;
            }
#pragma unroll
            for (int mm = 0; mm < 4; ++mm)
#pragma unroll
                for (int nn = 0; nn < TN; ++nn)
                    acc[mm][nn] = fmaf(av[mm], bv[nn], acc[mm][nn]);
        }
    }
#pragma unroll
    for (int mm = 0; mm < 4; ++mm) {
        int m = m0 + tm * 4 + mm;
        if (m < K) {
            int c = m / 27;
            int s = m - c * 27;
            float* dst = Wf + (s * C + c) * O + n0 + tn * TN;
#pragma unroll
            for (int nn = 0; nn < TN; ++nn) {
                int n = n0 + tn * TN + nn;
                if (n < O) dst[nn] = acc[mm][nn];
            }
        }
    }
}

// ---------------- big fused-weight GEMM (layers 3-5), FFMA2 + double buffer --
template <int BM, int BN, int TM, int TN, int KC, int THREADS, int MINB>
__global__ void __launch_bounds__(THREADS, MINB)
fusew2_kernel(const float* __restrict__ proj, const float* __restrict__ alpha,
              float* __restrict__ Wf, int K, int C, int O) {
    constexpr int NCOL = BN / TN;
    constexpr int TNH = TN / 2;
    constexpr int NCHUNK = 512 / KC;
    constexpr int A4 = BM * KC / 4;
    constexpr int NA = (A4 + THREADS - 1) / THREADS;
    constexpr int B4 = BN * KC / 4;
    constexpr int NB = (B4 + THREADS - 1) / THREADS;
    __shared__ alignas(16) float As[2][KC][BM];
    __shared__ alignas(16) float Bs[2][KC][BN];
    const int m0 = blockIdx.x * BM;
    const int n0 = blockIdx.y * BN;
    const int tid = threadIdx.x;
    const int col = tid % NCOL, row = tid / NCOL;
    const int rowBase = row * TM, colBase = col * TN;

    ull_t acc[TM][TNH];
#pragma unroll
    for (int a = 0; a < TM; a++)
#pragma unroll
        for (int b = 0; b < TNH; b++) acc[a][b] = 0ULL;

    float4 stA[NA], stB[NB];
    auto gather = [&](int j) {
        int p0 = j * KC;
#pragma unroll
        for (int t = 0; t < NA; t++) {
            int q = tid + t * THREADS;
            float4 v = make_float4(0.f, 0.f, 0.f, 0.f);
            if (A4 % THREADS == 0 || q < A4) {
                int i4 = q % (BM / 4);
                int pp = q / (BM / 4);
                int m = m0 + i4 * 4;
                if (m < K) v = *reinterpret_cast<const float4*>(proj + (size_t)(p0 + pp) * K + m);
            }
            stA[t] = v;
        }
#pragma unroll
        for (int t = 0; t < NB; t++) {
            int q = tid + t * THREADS;
            float4 v = make_float4(0.f, 0.f, 0.f, 0.f);
            if (B4 % THREADS == 0 || q < B4) {
                int cc = q / (BN / 4);
                int c4 = q % (BN / 4);
                v = *reinterpret_cast<const float4*>(alpha + (size_t)(p0 + cc) * O + n0 + c4 * 4);
            }
            stB[t] = v;
        }
    };
    auto commit = [&](int buf) {
#pragma unroll
        for (int t = 0; t < NA; t++) {
            int q = tid + t * THREADS;
            if (A4 % THREADS == 0 || q < A4) {
                int i4 = q % (BM / 4);
                int pp = q / (BM / 4);
                *reinterpret_cast<float4*>(&As[buf][pp][i4 * 4]) = stA[t];
            }
        }
#pragma unroll
        for (int t = 0; t < NB; t++) {
            int q = tid + t * THREADS;
            if (B4 % THREADS == 0 || q < B4) {
                int cc = q / (BN / 4);
                int c4 = q % (BN / 4);
                *reinterpret_cast<float4*>(&Bs[buf][cc][c4 * 4]) = stB[t];
            }
        }
    };

    gather(0);
    commit(0);
    __syncthreads();
    int cur = 0;
    for (int j = 0; j < NCHUNK; ++j) {
        if (j + 1 < NCHUNK) gather(j + 1);
#pragma unroll
        for (int cc = 0; cc < KC; ++cc) {
            float a[TM];
#pragma unroll
            for (int f = 0; f < TM; f += 4)
                *reinterpret_cast<float4*>(&a[f]) =
                    *reinterpret_cast<const float4*>(&As[cur][cc][rowBase + f]);
            ull_t bp[TNH];
            ulonglong2 b0 = *reinterpret_cast<const ulonglong2*>(&Bs[cur][cc][colBase]);
            ulonglong2 b1 = *reinterpret_cast<const ulonglong2*>(&Bs[cur][cc][colBase + 4]);
            bp[0] = b0.x; bp[1] = b0.y; bp[2] = b1.x; bp[3] = b1.y;
#pragma unroll
            for (int mm = 0; mm < TM; mm++) {
                ull_t ap;
                PACK2(ap, a[mm]);
#pragma unroll
                for (int p = 0; p < TNH; p++) FMA2(acc[mm][p], ap, bp[p]);
            }
        }
        if (j + 1 < NCHUNK) commit(cur ^ 1);
        __syncthreads();
        cur ^= 1;
    }

#pragma unroll
    for (int mm = 0; mm < TM; mm++) {
        int m = m0 + rowBase + mm;
        if (m < K) {
            int c = m / 27;
            int s = m - c * 27;
            ull_t* dst = reinterpret_cast<ull_t*>(Wf + ((size_t)(s * C + c)) * O + n0 + colBase);
#pragma unroll
            for (int p = 0; p < TNH; p++) dst[p] = acc[mm][p];
        }
    }
}

// ---------------- layer-1 direct conv (C=3, O=24), writes RAW sums ----------
__global__ void conv1_kernel(const float* __restrict__ X, const float* __restrict__ Wf,
                             float* __restrict__ Y) {
    __shared__ alignas(16) float sW[81 * 24];
    for (int i = threadIdx.x; i < 81 * 24; i += 256) sW[i] = Wf[i];
    __syncthreads();
    int m = blockIdx.x * 256 + threadIdx.x;  // M = 401408 exact
    int w = m % 112;
    int t = m / 112;
    int h = t % 112;
    t /= 112;
    int d = t % 16;
    ull_t acc[12];
#pragma unroll
    for (int p = 0; p < 12; p++) acc[p] = 0ULL;
    const float* base = X + (size_t)m * 3;
#pragma unroll
    for (int s = 0; s < 27; s++) {
        const int dz = s / 9 - 1, dy = (s / 3) % 3 - 1, dx = s % 3 - 1;
        int dd = d + dz, hh = h + dy, ww = w + dx;
        float x0 = 0.f, x1 = 0.f, x2 = 0.f;
        if ((unsigned)dd < 16u && (unsigned)hh < 112u && (unsigned)ww < 112u) {
            const float* px = base + ((dz * 112 + dy) * 112 + dx) * 3;
            x0 = px[0]; x1 = px[1]; x2 = px[2];
        }
        float xv[3] = {x0, x1, x2};
#pragma unroll
        for (int c = 0; c < 3; c++) {
            ull_t xp;
            PACK2(xp, xv[c]);
            const ulonglong2* wr = reinterpret_cast<const ulonglong2*>(&sW[(s * 3 + c) * 24]);
#pragma unroll
            for (int p2 = 0; p2 < 6; p2++) {
                ulonglong2 wv = wr[p2];
                FMA2(acc[2 * p2], xp, wv.x);
                FMA2(acc[2 * p2 + 1], xp, wv.y);
            }
        }
    }
    ull_t* dst = reinterpret_cast<ull_t*>(Y + (size_t)m * 24);
#pragma unroll
    for (int p = 0; p < 12; p++) dst[p] = acc[p];
}

// ---------------- implicit-GEMM conv: FFMA2, double buffer, split-K ----------
// BN of the PREVIOUS layer fused into the A-gather (x*scale[c]+shift[c],
// zeros stay zero for padding — matches reference BN-then-pad order).
// X: [B,D,H,W,C], Wf: [27*C][O] (row = s*C+c), Yp: S partial slices (RAW sums)
template <int BM, int BN, int TM, int TN, int KC, int C, int THREADS, bool BNIN>
__global__ void __launch_bounds__(THREADS, 2)
conv2_kernel(const float* __restrict__ X, const float* __restrict__ Wf,
             float* __restrict__ Yp, const float* __restrict__ scl,
             const float* __restrict__ shf,
             int B_, int D, int H, int W, int O, int S) {
    constexpr int NCOL = BN / TN;
    constexpr int CPT = C / KC;
    constexpr int TNH = TN / 2;
    constexpr int A4 = BM * KC / 4;
    constexpr int NA = (A4 + THREADS - 1) / THREADS;
    constexpr int B4 = BN * KC / 4;
    constexpr int NB = (B4 + THREADS - 1) / THREADS;
    __shared__ alignas(16) float As[2][KC][BM];
    __shared__ alignas(16) float Bs[2][KC][BN];
    __shared__ int sBase[BM];
    __shared__ int sDHW[BM];
    __shared__ alignas(16) float sScale[BNIN ? C : 4];
    __shared__ alignas(16) float sShift[BNIN ? C : 4];
    const int M = B_ * D * H * W;
    const int m0 = blockIdx.x * BM;
    const int n0 = blockIdx.y * BN;
    const int z = blockIdx.z;
    const int s0 = (27 * z) / S, s1 = (27 * (z + 1)) / S;
    const int nChunks = (s1 - s0) * CPT;
    const int tid = threadIdx.x;
    const int col = tid % NCOL, row = tid / NCOL;
    const int rowBase = row * TM, colBase = col * TN;

    if constexpr (BNIN) {
        for (int i = tid; i < C; i += THREADS) {
            sScale[i] = scl[i];
            sShift[i] = shf[i];
        }
    }
    for (int i = tid; i < BM; i += THREADS) {
        int m = m0 + i;
        if (m < M) {
            int w = m % W;
            int t = m / W;
            int h = t % H;
            t /= H;
            int d = t % D;
            sBase[i] = m * C;
            sDHW[i] = (d << 20) | (h << 10) | w;
        } else {
            sBase[i] = -1;
            sDHW[i] = 0;
        }
    }
    __syncthreads();

    ull_t acc[TM][TNH];
#pragma unroll
    for (int a = 0; a < TM; a++)
#pragma unroll
        for (int b = 0; b < TNH; b++) acc[a][b] = 0ULL;

    float4 stA[NA], stB[NB];
    auto gather = [&](int j) {
        int s = s0 + j / CPT;
        int c0 = (j % CPT) * KC;
        int dz = s / 9 - 1, dy = (s / 3) % 3 - 1, dx = s % 3 - 1;
        int koff = ((dz * H + dy) * W + dx) * C + c0;
#pragma unroll
        for (int t = 0; t < NA; t++) {
            int q = tid + t * THREADS;
            float4 v = make_float4(0.f, 0.f, 0.f, 0.f);
            if (A4 % THREADS == 0 || q < A4) {
                int i = q % BM;
                int cc4 = q / BM;
                int bs = sBase[i];
                if (bs >= 0) {
                    int dhw = sDHW[i];
                    int dd = (dhw >> 20) + dz;
                    int hh = ((dhw >> 10) & 1023) + dy;
                    int ww = (dhw & 1023) + dx;
                    if ((unsigned)dd < (unsigned)D && (unsigned)hh < (unsigned)H &&
                        (unsigned)ww < (unsigned)W) {
                        v = *reinterpret_cast<const float4*>(X + bs + koff + cc4 * 4);
                        if constexpr (BNIN) {
                            int ch = c0 + cc4 * 4;
                            float4 sc = *reinterpret_cast<const float4*>(&sScale[ch]);
                            float4 sh = *reinterpret_cast<const float4*>(&sShift[ch]);
                            v.x = fmaf(v.x, sc.x, sh.x);
                            v.y = fmaf(v.y, sc.y, sh.y);
                            v.z = fmaf(v.z, sc.z, sh.z);
                            v.w = fmaf(v.w, sc.w, sh.w);
                        }
                    }
                }
            }
            stA[t] = v;
        }
        const float* wb = Wf + ((size_t)(s * C + c0)) * O + n0;
#pragma unroll
        for (int t = 0; t < NB; t++) {
            int q = tid + t * THREADS;
            float4 v = make_float4(0.f, 0.f, 0.f, 0.f);
            if (B4 % THREADS == 0 || q < B4) {
                int cc = q / (BN / 4);
                int c4 = q % (BN / 4);
                v = *reinterpret_cast<const float4*>(wb + (size_t)cc * O + c4 * 4);
            }
            stB[t] = v;
        }
    };
    auto commit = [&](int buf) {
#pragma unroll
        for (int t = 0; t < NA; t++) {
            int q = tid + t * THREADS;
            if (A4 % THREADS == 0 || q < A4) {
                int i = q % BM;
                int cc = (q / BM) * 4;
                As[buf][cc + 0][i] = stA[t].x;
                As[buf][cc + 1][i] = stA[t].y;
                As[buf][cc + 2][i] = stA[t].z;
                As[buf][cc + 3][i] = stA[t].w;
            }
        }
#pragma unroll
        for (int t = 0; t < NB; t++) {
            int q = tid + t * THREADS;
            if (B4 % THREADS == 0 || q < B4) {
                int cc = q / (BN / 4);
                int c4 = q % (BN / 4);
                *reinterpret_cast<float4*>(&Bs[buf][cc][c4 * 4]) = stB[t];
            }
        }
    };

    gather(0);
    commit(0);
    __syncthreads();
    int cur = 0;
    for (int j = 0; j < nChunks; ++j) {
        if (j + 1 < nChunks) gather(j + 1);
#pragma unroll
        for (int cc = 0; cc < KC; ++cc) {
            float a[TM];
            *reinterpret_cast<float4*>(&a[0]) = *reinterpret_cast<const float4*>(&As[cur][cc][rowBase]);
            *reinterpret_cast<float4*>(&a[4]) = *reinterpret_cast<const float4*>(&As[cur][cc][rowBase + 4]);
            ull_t bp[TNH];
            if constexpr (TN == 8) {
                ulonglong2 b0 = *reinterpret_cast<const ulonglong2*>(&Bs[cur][cc][colBase]);
                ulonglong2 b1 = *reinterpret_cast<const ulonglong2*>(&Bs[cur][cc][colBase + 4]);
                bp[0] = b0.x; bp[1] = b0.y; bp[2] = b1.x; bp[3] = b1.y;
            } else {
                const ull_t* pb = reinterpret_cast<const ull_t*>(&Bs[cur][cc][colBase]);
#pragma unroll
                for (int p = 0; p < TNH; p++) bp[p] = pb[p];
            }
#pragma unroll
            for (int mm = 0; mm < TM; mm++) {
                ull_t ap;
                PACK2(ap, a[mm]);
#pragma unroll
                for (int p = 0; p < TNH; p++) FMA2(acc[mm][p], ap, bp[p]);
            }
        }
        if (j + 1 < nChunks) commit(cur ^ 1);
        __syncthreads();
        cur ^= 1;
    }

    float* out = Yp + (size_t)z * M * O;
#pragma unroll
    for (int mm = 0; mm < TM; mm++) {
        int m = m0 + rowBase + mm;
        if (m < M) {
            ull_t* dst = reinterpret_cast<ull_t*>(out + (size_t)m * O + n0 + colBase);
#pragma unroll
            for (int p = 0; p < TNH; p++) dst[p] = acc[mm][p];
        }
    }
}

// ------ split-K reduce + clamp(1+x,0) + maxpool (1,2,2) + sum/sumsq ----------
// Writes PRE-BN pooled activations; BN affine is applied downstream in the
// next conv's gather (or in FC1 for the last layer).
__global__ void pool_stats_kernel(const float* __restrict__ Y, float* __restrict__ P,
                                  float* __restrict__ gsum, float* __restrict__ gsq,
                                  int B, int D, int H, int W, int O, int Hp, int Wp,
                                  int S, int sliceStride) {
    __shared__ float ssum[384];
    __shared__ float ssq[384];
    int tid = threadIdx.x;
    for (int o = tid; o < O; o += blockDim.x) { ssum[o] = 0.f; ssq[o] = 0.f; }
    __syncthreads();
    int Ne = B * D * Hp * Wp * O;
    int stride = gridDim.x * blockDim.x;
    for (int e = blockIdx.x * blockDim.x + tid; e < Ne; e += stride) {
        int o = e % O;
        int m = e / O;
        int wp = m % Wp;
        int t = m / Wp;
        int hp = t % Hp;
        t /= Hp;
        int d = t % D;
        int b = t / D;
        size_t off = ((size_t)(((b * D + d) * H + hp * 2) * W) + wp * 2) * O + o;
        float v0 = 0.f, v1 = 0.f, v2 = 0.f, v3 = 0.f;
        for (int s = 0; s < S; s++) {
            const float* src = Y + off + (size_t)s * sliceStride;
            v0 += src[0];
            v1 += src[O];
            v2 += src[(size_t)W * O];
            v3 += src[(size_t)W * O + O];
        }
        float v = fmaxf(fmaxf(v0, v1), fmaxf(v2, v3));
        v = fmaxf(1.f + v, 0.f);
        P[e] = v;
        atomicAdd(&ssum[o], v);
        atomicAdd(&ssq[o], v * v);
    }
    __syncthreads();
    for (int o = tid; o < O; o += blockDim.x) {
        atomicAdd(&gsum[o], ssum[o]);
        atomicAdd(&gsq[o], ssq[o]);
    }
}

// Computes scale/shift, then RE-ZEROES the stat buffers for the next layer
// (stream-ordered before the next pool; deterministic across graph replays).
__global__ void bn_final_kernel(float* __restrict__ sum, float* __restrict__ sq,
                                const float* __restrict__ gamma, const float* __restrict__ beta,
                                float* __restrict__ scale, float* __restrict__ shift,
                                float invN, int O) {
    int o = threadIdx.x;
    if (o < O) {
        float mean = sum[o] * invN;
        float var = sq[o] * invN - mean * mean;
        float sc = gamma[o] * rsqrtf(var + 1e-5f);
        scale[o] = sc;
        shift[o] = beta[o] - mean * sc;
    }
    if (o < 384) { sum[o] = 0.f; sq[o] = 0.f; }
}

// ---------------- FC layers --------------------------------------------------
// v: pooled L5 (pre-BN); BN affine applied inline here.
__global__ void fc1_kernel(const float* __restrict__ v, const float* __restrict__ w1,
                           const float* __restrict__ b1,
                           const float* __restrict__ scale, const float* __restrict__ shift,
                           float* __restrict__ out) {
    __shared__ float s0[256];
    __shared__ float s1[256];
    __shared__ float sSc[384];
    __shared__ float sSh[384];
    int j = blockIdx.x;
    int tid = threadIdx.x;
    for (int o = tid; o < 384; o += 256) { sSc[o] = scale[o]; sSh[o] = shift[o]; }
    __syncthreads();
    const float* wr = w1 + (size_t)j * 55296;
    float a0 = 0.f, a1 = 0.f;
    for (int k = tid; k < 55296; k += 256) {
        int o = k / 144;
        int r = k - o * 144;
        int idx = r * 384 + o;
        float sc = sSc[o], sh = sSh[o];
        float wv = wr[k];
        a0 += wv * fmaf(v[idx], sc, sh);
        a1 += wv * fmaf(v[idx + 55296], sc, sh);
    }
    s0[tid] = a0; s1[tid] = a1;
    __syncthreads();
    for (int t = 128; t > 0; t >>= 1) {
        if (tid < t) { s0[tid] += s0[tid + t]; s1[tid] += s1[tid + t]; }
        __syncthreads();
    }
    if (tid == 0) {
        out[j] = fmaxf(s0[0] + b1[j], 0.f);
        out[512 + j] = fmaxf(s1[0] + b1[j], 0.f);
    }
}

__global__ void fc2_kernel(const float* __restrict__ in, const float* __restrict__ w2,
                           const float* __restrict__ b2, float* __restrict__ out) {
    __shared__ float s0[128];
    __shared__ float s1[128];
    int i = blockIdx.x;
    int tid = threadIdx.x;
    float a0 = 0.f, a1 = 0.f;
    for (int j = tid; j < 512; j += 128) {
        float wv = w2[i * 512 + j];
        a0 += wv * in[j];
        a1 += wv * in[512 + j];
    }
    s0[tid] = a0; s1[tid] = a1;
    __syncthreads();
    for (int t = 64; t > 0; t >>= 1) {
        if (tid < t) { s0[tid] += s0[tid + t]; s1[tid] += s1[tid + t]; }
        __syncthreads();
    }
    if (tid == 0) {
        out[i] = fmaxf(s0[0] + b2[i], 0.f);
        out[256 + i] = fmaxf(s1[0] + b2[i], 0.f);
    }
}

__global__ void fc3_kernel(const float* __restrict__ in, const float* __restrict__ w3,
                           const float* __restrict__ b3, float* __restrict__ out) {
    __shared__ float s0[128];
    __shared__ float s1[128];
    int i = blockIdx.x;
    int tid = threadIdx.x;
    float a0 = 0.f, a1 = 0.f;
    for (int j = tid; j < 256; j += 128) {
        float wv = w3[i * 256 + j];
        a0 += wv * in[j];
        a1 += wv * in[256 + j];
    }
    s0[tid] = a0; s1[tid] = a1;
    __syncthreads();
    for (int t = 64; t > 0; t >>= 1) {
        if (tid < t) { s0[tid] += s0[tid + t]; s1[tid] += s1[tid + t]; }
        __syncthreads();
    }
    if (tid == 0) {
        out[i] = s0[0] + b3[i];
        out[101 + i] = s1[0] + b3[i];
    }
}

// ---------------- driver ------------------------------------------------------
extern "C" void kernel_launch(void* const* d_in, const int* in_sizes, int n_in,
                              void* d_out, int out_size) {
    const float* x = (const float*)d_in[0];
    const float* Pj[5];
    const float* Al[5];
    const float* Ga[5];
    const float* Be[5];
    for (int i = 0; i < 5; i++) {
        Pj[i] = (const float*)d_in[1 + 4 * i];
        Al[i] = (const float*)d_in[2 + 4 * i];
        Ga[i] = (const float*)d_in[3 + 4 * i];
        Be[i] = (const float*)d_in[4 + 4 * i];
    }
    const float* w1 = (const float*)d_in[21];
    const float* b1 = (const float*)d_in[22];
    const float* w2 = (const float*)d_in[23];
    const float* b2 = (const float*)d_in[24];
    const float* w3 = (const float*)d_in[25];
    const float* b3 = (const float*)d_in[26];

    float *preact, *act, *wf1, *wf2, *wf3, *wf4, *wf5;
    float *sum, *sq, *scale, *shift, *fc1b, *fc2b;
    cudaGetSymbolAddress((void**)&preact, g_preact);
    cudaGetSymbolAddress((void**)&act, g_act);
    cudaGetSymbolAddress((void**)&wf1, g_wf1);
    cudaGetSymbolAddress((void**)&wf2, g_wf2);
    cudaGetSymbolAddress((void**)&wf3, g_wf3);
    cudaGetSymbolAddress((void**)&wf4, g_wf4);
    cudaGetSymbolAddress((void**)&wf5, g_wf5);
    cudaGetSymbolAddress((void**)&sum, g_sum);
    cudaGetSymbolAddress((void**)&sq, g_sumsq);
    cudaGetSymbolAddress((void**)&scale, g_scale);
    cudaGetSymbolAddress((void**)&shift, g_shift);
    cudaGetSymbolAddress((void**)&fc1b, g_fc1);
    cudaGetSymbolAddress((void**)&fc2b, g_fc2);

    // idx 0: input transpose to channel-last (+ upfront stats zero)
    {
        int N = 2 * 3 * 16 * 112 * 112;
        nchw2nhwc_kernel<<<(N + 255) / 256, 256>>>(x, act, sum, sq);
    }

    // idx 1-2: small fusew GEMMs
    fusew_kernel<32, 2><<<dim3(2, 1), 256>>>(Pj[0], Al[0], wf1, 81, 3, 24);
    fusew_kernel<64, 4><<<dim3(11, 1), 256>>>(Pj[1], Al[1], wf2, 648, 24, 48);

    // idx 3 (PROFILED): fusew2-L5 A/B — 256 threads, BM128/BN128, 123 blocks
    // = exactly one wave at 1 block/SM, 8 warps/SM. Compare vs 89.6us @192t.
    fusew2_kernel<128, 128, 8, 8, 16, 256, 1>
        <<<dim3(41, 3), 256>>>(Pj[4], Al[4], wf5, 5184, 192, 384);

    // idx 4-5: fusew2 L3/L4 at exact R9 config (192t, TM8, minB 2)
    fusew2_kernel<128, 96, 8, 8, 16, 192, 2>
        <<<dim3(11, 1), 192>>>(Pj[2], Al[2], wf3, 1296, 48, 96);
    fusew2_kernel<128, 96, 8, 8, 16, 192, 2>
        <<<dim3(21, 2), 192>>>(Pj[3], Al[3], wf4, 2592, 96, 192);

    const int B = 2, D = 16;

    auto do_pool_bn = [&](int C_H, int C_W, int C_O, int C_S, int C_M,
                          const float* gamma, const float* beta) {
        int hp = (C_H - 2) / 2 + 1;
        int wp = (C_W - 2) / 2 + 1;
        int ne = B * D * hp * wp * C_O;
        int pb = (ne + 255) / 256;
        if (pb > 4096) pb = 4096;
        pool_stats_kernel<<<pb, 256>>>(preact, act, sum, sq, B, D, C_H, C_W, C_O, hp, wp,
                                       C_S, C_M * C_O);
        float invN = 1.f / (float)(B * D * hp * wp);
        bn_final_kernel<<<1, 384>>>(sum, sq, gamma, beta, scale, shift, invN, C_O);
    };

    // ---------------- layer 1: C=3, O=24, H=W=112 (no BN on input) ----------
    conv1_kernel<<<1568, 256>>>(act, wf1, preact);
    do_pool_bn(112, 112, 24, 1, 2 * 16 * 112 * 112, Ga[0], Be[0]);

    // ---------------- layer 2: C=24, O=48, H=W=56 (R9 tiles) ----------------
    int M = 2 * 16 * 56 * 56;
    conv2_kernel<128, 48, 8, 6, 8, 24, 128, true>
        <<<dim3(M / 128, 1, 1), 128>>>(act, wf2, preact, scale, shift, B, D, 56, 56, 48, 1);
    do_pool_bn(56, 56, 48, 1, M, Ga[1], Be[1]);

    // ---------------- layer 3: C=48, O=96, H=W=28, split-K=3 ----------------
    M = 2 * 16 * 28 * 28;
    conv2_kernel<128, 96, 8, 8, 16, 48, 192, true>
        <<<dim3(M / 128, 1, 3), 192>>>(act, wf3, preact, scale, shift, B, D, 28, 28, 96, 3);
    do_pool_bn(28, 28, 96, 3, M, Ga[2], Be[2]);

    // ---------------- layer 4: C=96, O=192, H=W=14, split-K=3 ---------------
    M = 2 * 16 * 14 * 14;
    conv2_kernel<128, 96, 8, 8, 16, 96, 192, true>
        <<<dim3(M / 128, 2, 3), 192>>>(act, wf4, preact, scale, shift, B, D, 14, 14, 192, 3);
    do_pool_bn(14, 14, 192, 3, M, Ga[3], Be[3]);

    // ---------------- layer 5: C=192, O=384, H=W=7, split-K=3 (one wave) ----
    M = 2 * 16 * 7 * 7;
    conv2_kernel<64, 128, 8, 8, 16, 192, 128, true>
        <<<dim3((M + 63) / 64, 3, 3), 128>>>(act, wf5, preact, scale, shift, B, D, 7, 7, 384, 3);
    do_pool_bn(7, 7, 384, 3, M, Ga[4], Be[4]);

    // ---------------- FC head (L5 BN fused into FC1 input) ------------------
    fc1_kernel<<<512, 256>>>(act, w1, b1, scale, shift, fc1b);
    fc2_kernel<<<256, 128>>>(fc1b, w2, b2, fc2b);
    fc3_kernel<<<101, 128>>>(fc2b, w3, b3, (float*)d_out);
}

// round 14
// speedup vs baseline: 1.1186x; 1.0306x over previous
#include <cuda_runtime.h>

typedef unsigned long long ull_t;

// ---------------- scratch (static device globals; no allocation) ------------
__device__ float g_preact[9633792];   // max partial store: L1 2*16*112*112*24
__device__ float g_act[2408448];      // max pooled/layer-input: 2*16*56*56*24
__device__ float g_wf[1990656];       // max fused weight: 5184*384
__device__ float g_sum[384];
__device__ float g_sumsq[384];
__device__ float g_scale[384];
__device__ float g_shift[384];
__device__ float g_fc1[1024];
__device__ float g_fc2[512];

#define PACK2(d, s) asm("mov.b64 %0, {%1, %1};" : "=l"(d) : "f"(s))
#define FMA2(d, a, b) asm("fma.rn.f32x2 %0, %1, %2, %0;" : "+l"(d) : "l"(a), "l"(b))

// ---------------- input transpose: (2,3,16,112,112) -> (2,16,112,112,3) -----
__global__ void nchw2nhwc_kernel(const float* __restrict__ x, float* __restrict__ out,
                                 float* __restrict__ sum, float* __restrict__ sq) {
    const int DHW = 16 * 112 * 112;
    const int N = 2 * DHW * 3;
    int e = blockIdx.x * blockDim.x + threadIdx.x;
    if (e < 384) { sum[e] = 0.f; sq[e] = 0.f; }   // upfront stats zero
    if (e >= N) return;
    int c = e % 3;
    int m = e / 3;
    int b = m / DHW;
    int r = m - b * DHW;
    out[e] = x[(b * 3 + c) * DHW + r];
}

// ---------------- small fused-weight GEMM (layers 1-2) ----------------------
// Wf[s*C+c][o] = sum_p proj[p][c*27+s] * alpha[p][o]
template <int BN, int TN>
__global__ void fusew_kernel(const float* __restrict__ proj, const float* __restrict__ alpha,
                             float* __restrict__ Wf, int K, int C, int O) {
    constexpr int BM = 64, KC = 16;
    __shared__ alignas(16) float As[KC][BM];
    __shared__ alignas(16) float Bs[KC][BN];
    const int m0 = blockIdx.x * BM;
    const int n0 = blockIdx.y * BN;
    const int tid = threadIdx.x;
    const int tm = tid >> 4;
    const int tn = tid & 15;

    float acc[4][TN];
#pragma unroll
    for (int i = 0; i < 4; i++)
#pragma unroll
        for (int j = 0; j < TN; j++) acc[i][j] = 0.f;

    for (int p0 = 0; p0 < 512; p0 += KC) {
        __syncthreads();
        for (int idx = tid; idx < KC * BM; idx += 256) {
            int pp = idx / BM, i = idx - pp * BM;
            int m = m0 + i;
            As[pp][i] = (m < K) ? proj[(p0 + pp) * K + m] : 0.f;
        }
        for (int idx = tid; idx < KC * BN; idx += 256) {
            int pp = idx / BN, j = idx - pp * BN;
            int n = n0 + j;
            Bs[pp][j] = (n < O) ? alpha[(p0 + pp) * O + n] : 0.f;
        }
        __syncthreads();
#pragma unroll
        for (int pp = 0; pp < KC; ++pp) {
            float4 a4 = *(const float4*)&As[pp][tm * 4];
            float av[4] = {a4.x, a4.y, a4.z, a4.w};
            float bv[TN];
            if constexpr (TN == 4) {
                float4 b4 = *(const float4*)&Bs[pp][tn * 4];
                bv[0] = b4.x; bv[1] = b4.y; bv[2] = b4.z; bv[3] = b4.w;
            } else {
                float2 b2 = *(const float2*)&Bs[pp][tn * 2];
                bv[0] = b2.x; bv[1] = b2.y;
            }
#pragma unroll
            for (int mm = 0; mm < 4; ++mm)
#pragma unroll
                for (int nn = 0; nn < TN; ++nn)
                    acc[mm][nn] = fmaf(av[mm], bv[nn], acc[mm][nn]);
        }
    }
#pragma unroll
    for (int mm = 0; mm < 4; ++mm) {
        int m = m0 + tm * 4 + mm;
        if (m < K) {
            int c = m / 27;
            int s = m - c * 27;
            float* dst = Wf + (s * C + c) * O + n0 + tn * TN;
#pragma unroll
            for (int nn = 0; nn < TN; ++nn) {
                int n = n0 + tn * TN + nn;
                if (n < O) dst[nn] = acc[mm][nn];
            }
        }
    }
}

// ---------------- big fused-weight GEMM (layers 3-5), FFMA2 + double buffer --
template <int BM, int BN, int TM, int TN, int KC, int THREADS, int MINB>
__global__ void __launch_bounds__(THREADS, MINB)
fusew2_kernel(const float* __restrict__ proj, const float* __restrict__ alpha,
              float* __restrict__ Wf, int K, int C, int O) {
    constexpr int NCOL = BN / TN;
    constexpr int TNH = TN / 2;
    constexpr int NCHUNK = 512 / KC;
    constexpr int A4 = BM * KC / 4;
    constexpr int NA = (A4 + THREADS - 1) / THREADS;
    constexpr int B4 = BN * KC / 4;
    constexpr int NB = (B4 + THREADS - 1) / THREADS;
    __shared__ alignas(16) float As[2][KC][BM];
    __shared__ alignas(16) float Bs[2][KC][BN];
    const int m0 = blockIdx.x * BM;
    const int n0 = blockIdx.y * BN;
    const int tid = threadIdx.x;
    const int col = tid % NCOL, row = tid / NCOL;
    const int rowBase = row * TM, colBase = col * TN;

    ull_t acc[TM][TNH];
#pragma unroll
    for (int a = 0; a < TM; a++)
#pragma unroll
        for (int b = 0; b < TNH; b++) acc[a][b] = 0ULL;

    float4 stA[NA], stB[NB];
    auto gather = [&](int j) {
        int p0 = j * KC;
#pragma unroll
        for (int t = 0; t < NA; t++) {
            int q = tid + t * THREADS;
            float4 v = make_float4(0.f, 0.f, 0.f, 0.f);
            if (A4 % THREADS == 0 || q < A4) {
                int i4 = q % (BM / 4);
                int pp = q / (BM / 4);
                int m = m0 + i4 * 4;
                if (m < K) v = *reinterpret_cast<const float4*>(proj + (size_t)(p0 + pp) * K + m);
            }
            stA[t] = v;
        }
#pragma unroll
        for (int t = 0; t < NB; t++) {
            int q = tid + t * THREADS;
            float4 v = make_float4(0.f, 0.f, 0.f, 0.f);
            if (B4 % THREADS == 0 || q < B4) {
                int cc = q / (BN / 4);
                int c4 = q % (BN / 4);
                v = *reinterpret_cast<const float4*>(alpha + (size_t)(p0 + cc) * O + n0 + c4 * 4);
            }
            stB[t] = v;
        }
    };
    auto commit = [&](int buf) {
#pragma unroll
        for (int t = 0; t < NA; t++) {
            int q = tid + t * THREADS;
            if (A4 % THREADS == 0 || q < A4) {
                int i4 = q % (BM / 4);
                int pp = q / (BM / 4);
                *reinterpret_cast<float4*>(&As[buf][pp][i4 * 4]) = stA[t];
            }
        }
#pragma unroll
        for (int t = 0; t < NB; t++) {
            int q = tid + t * THREADS;
            if (B4 % THREADS == 0 || q < B4) {
                int cc = q / (BN / 4);
                int c4 = q % (BN / 4);
                *reinterpret_cast<float4*>(&Bs[buf][cc][c4 * 4]) = stB[t];
            }
        }
    };

    gather(0);
    commit(0);
    __syncthreads();
    int cur = 0;
    for (int j = 0; j < NCHUNK; ++j) {
        if (j + 1 < NCHUNK) gather(j + 1);
#pragma unroll
        for (int cc = 0; cc < KC; ++cc) {
            float a[TM];
#pragma unroll
            for (int f = 0; f < TM; f += 4)
                *reinterpret_cast<float4*>(&a[f]) =
                    *reinterpret_cast<const float4*>(&As[cur][cc][rowBase + f]);
            ull_t bp[TNH];
            ulonglong2 b0 = *reinterpret_cast<const ulonglong2*>(&Bs[cur][cc][colBase]);
            ulonglong2 b1 = *reinterpret_cast<const ulonglong2*>(&Bs[cur][cc][colBase + 4]);
            bp[0] = b0.x; bp[1] = b0.y; bp[2] = b1.x; bp[3] = b1.y;
#pragma unroll
            for (int mm = 0; mm < TM; mm++) {
                ull_t ap;
                PACK2(ap, a[mm]);
#pragma unroll
                for (int p = 0; p < TNH; p++) FMA2(acc[mm][p], ap, bp[p]);
            }
        }
        if (j + 1 < NCHUNK) commit(cur ^ 1);
        __syncthreads();
        cur ^= 1;
    }

#pragma unroll
    for (int mm = 0; mm < TM; mm++) {
        int m = m0 + rowBase + mm;
        if (m < K) {
            int c = m / 27;
            int s = m - c * 27;
            ull_t* dst = reinterpret_cast<ull_t*>(Wf + ((size_t)(s * C + c)) * O + n0 + colBase);
#pragma unroll
            for (int p = 0; p < TNH; p++) dst[p] = acc[mm][p];
        }
    }
}

// ---------------- layer-1 direct conv (C=3, O=24), writes RAW sums ----------
__global__ void conv1_kernel(const float* __restrict__ X, const float* __restrict__ Wf,
                             float* __restrict__ Y) {
    __shared__ alignas(16) float sW[81 * 24];
    for (int i = threadIdx.x; i < 81 * 24; i += 256) sW[i] = Wf[i];
    __syncthreads();
    int m = blockIdx.x * 256 + threadIdx.x;  // M = 401408 exact
    int w = m % 112;
    int t = m / 112;
    int h = t % 112;
    t /= 112;
    int d = t % 16;
    ull_t acc[12];
#pragma unroll
    for (int p = 0; p < 12; p++) acc[p] = 0ULL;
    const float* base = X + (size_t)m * 3;
#pragma unroll
    for (int s = 0; s < 27; s++) {
        const int dz = s / 9 - 1, dy = (s / 3) % 3 - 1, dx = s % 3 - 1;
        int dd = d + dz, hh = h + dy, ww = w + dx;
        float x0 = 0.f, x1 = 0.f, x2 = 0.f;
        if ((unsigned)dd < 16u && (unsigned)hh < 112u && (unsigned)ww < 112u) {
            const float* px = base + ((dz * 112 + dy) * 112 + dx) * 3;
            x0 = px[0]; x1 = px[1]; x2 = px[2];
        }
        float xv[3] = {x0, x1, x2};
#pragma unroll
        for (int c = 0; c < 3; c++) {
            ull_t xp;
            PACK2(xp, xv[c]);
            const ulonglong2* wr = reinterpret_cast<const ulonglong2*>(&sW[(s * 3 + c) * 24]);
#pragma unroll
            for (int p2 = 0; p2 < 6; p2++) {
                ulonglong2 wv = wr[p2];
                FMA2(acc[2 * p2], xp, wv.x);
                FMA2(acc[2 * p2 + 1], xp, wv.y);
            }
        }
    }
    ull_t* dst = reinterpret_cast<ull_t*>(Y + (size_t)m * 24);
#pragma unroll
    for (int p = 0; p < 12; p++) dst[p] = acc[p];
}

// ---------------- implicit-GEMM conv: FFMA2, double buffer, split-K ----------
// BN of the PREVIOUS layer fused into the A-gather (x*scale[c]+shift[c],
// zeros stay zero for padding — matches reference BN-then-pad order).
// X: [B,D,H,W,C], Wf: [27*C][O] (row = s*C+c), Yp: S partial slices (RAW sums)
template <int BM, int BN, int TM, int TN, int KC, int C, int THREADS, bool BNIN>
__global__ void __launch_bounds__(THREADS, 2)
conv2_kernel(const float* __restrict__ X, const float* __restrict__ Wf,
             float* __restrict__ Yp, const float* __restrict__ scl,
             const float* __restrict__ shf,
             int B_, int D, int H, int W, int O, int S) {
    constexpr int NCOL = BN / TN;
    constexpr int CPT = C / KC;
    constexpr int TNH = TN / 2;
    constexpr int A4 = BM * KC / 4;
    constexpr int NA = (A4 + THREADS - 1) / THREADS;
    constexpr int B4 = BN * KC / 4;
    constexpr int NB = (B4 + THREADS - 1) / THREADS;
    __shared__ alignas(16) float As[2][KC][BM];
    __shared__ alignas(16) float Bs[2][KC][BN];
    __shared__ int sBase[BM];
    __shared__ int sDHW[BM];
    __shared__ alignas(16) float sScale[BNIN ? C : 4];
    __shared__ alignas(16) float sShift[BNIN ? C : 4];
    const int M = B_ * D * H * W;
    const int m0 = blockIdx.x * BM;
    const int n0 = blockIdx.y * BN;
    const int z = blockIdx.z;
    const int s0 = (27 * z) / S, s1 = (27 * (z + 1)) / S;
    const int nChunks = (s1 - s0) * CPT;
    const int tid = threadIdx.x;
    const int col = tid % NCOL, row = tid / NCOL;
    const int rowBase = row * TM, colBase = col * TN;

    if constexpr (BNIN) {
        for (int i = tid; i < C; i += THREADS) {
            sScale[i] = scl[i];
            sShift[i] = shf[i];
        }
    }
    for (int i = tid; i < BM; i += THREADS) {
        int m = m0 + i;
        if (m < M) {
            int w = m % W;
            int t = m / W;
            int h = t % H;
            t /= H;
            int d = t % D;
            sBase[i] = m * C;
            sDHW[i] = (d << 20) | (h << 10) | w;
        } else {
            sBase[i] = -1;
            sDHW[i] = 0;
        }
    }
    __syncthreads();

    ull_t acc[TM][TNH];
#pragma unroll
    for (int a = 0; a < TM; a++)
#pragma unroll
        for (int b = 0; b < TNH; b++) acc[a][b] = 0ULL;

    float4 stA[NA], stB[NB];
    auto gather = [&](int j) {
        int s = s0 + j / CPT;
        int c0 = (j % CPT) * KC;
        int dz = s / 9 - 1, dy = (s / 3) % 3 - 1, dx = s % 3 - 1;
        int koff = ((dz * H + dy) * W + dx) * C + c0;
#pragma unroll
        for (int t = 0; t < NA; t++) {
            int q = tid + t * THREADS;
            float4 v = make_float4(0.f, 0.f, 0.f, 0.f);
            if (A4 % THREADS == 0 || q < A4) {
                int i = q % BM;
                int cc4 = q / BM;
                int bs = sBase[i];
                if (bs >= 0) {
                    int dhw = sDHW[i];
                    int dd = (dhw >> 20) + dz;
                    int hh = ((dhw >> 10) & 1023) + dy;
                    int ww = (dhw & 1023) + dx;
                    if ((unsigned)dd < (unsigned)D && (unsigned)hh < (unsigned)H &&
                        (unsigned)ww < (unsigned)W) {
                        v = *reinterpret_cast<const float4*>(X + bs + koff + cc4 * 4);
                        if constexpr (BNIN) {
                            int ch = c0 + cc4 * 4;
                            float4 sc = *reinterpret_cast<const float4*>(&sScale[ch]);
                            float4 sh = *reinterpret_cast<const float4*>(&sShift[ch]);
                            v.x = fmaf(v.x, sc.x, sh.x);
                            v.y = fmaf(v.y, sc.y, sh.y);
                            v.z = fmaf(v.z, sc.z, sh.z);
                            v.w = fmaf(v.w, sc.w, sh.w);
                        }
                    }
                }
            }
            stA[t] = v;
        }
        const float* wb = Wf + ((size_t)(s * C + c0)) * O + n0;
#pragma unroll
        for (int t = 0; t < NB; t++) {
            int q = tid + t * THREADS;
            float4 v = make_float4(0.f, 0.f, 0.f, 0.f);
            if (B4 % THREADS == 0 || q < B4) {
                int cc = q / (BN / 4);
                int c4 = q % (BN / 4);
                v = *reinterpret_cast<const float4*>(wb + (size_t)cc * O + c4 * 4);
            }
            stB[t] = v;
        }
    };
    auto commit = [&](int buf) {
#pragma unroll
        for (int t = 0; t < NA; t++) {
            int q = tid + t * THREADS;
            if (A4 % THREADS == 0 || q < A4) {
                int i = q % BM;
                int cc = (q / BM) * 4;
                As[buf][cc + 0][i] = stA[t].x;
                As[buf][cc + 1][i] = stA[t].y;
                As[buf][cc + 2][i] = stA[t].z;
                As[buf][cc + 3][i] = stA[t].w;
            }
        }
#pragma unroll
        for (int t = 0; t < NB; t++) {
            int q = tid + t * THREADS;
            if (B4 % THREADS == 0 || q < B4) {
                int cc = q / (BN / 4);
                int c4 = q % (BN / 4);
                *reinterpret_cast<float4*>(&Bs[buf][cc][c4 * 4]) = stB[t];
            }
        }
    };

    gather(0);
    commit(0);
    __syncthreads();
    int cur = 0;
    for (int j = 0; j < nChunks; ++j) {
        if (j + 1 < nChunks) gather(j + 1);
#pragma unroll
        for (int cc = 0; cc < KC; ++cc) {
            float a[TM];
            *reinterpret_cast<float4*>(&a[0]) = *reinterpret_cast<const float4*>(&As[cur][cc][rowBase]);
            *reinterpret_cast<float4*>(&a[4]) = *reinterpret_cast<const float4*>(&As[cur][cc][rowBase + 4]);
            ull_t bp[TNH];
            if constexpr (TN == 8) {
                ulonglong2 b0 = *reinterpret_cast<const ulonglong2*>(&Bs[cur][cc][colBase]);
                ulonglong2 b1 = *reinterpret_cast<const ulonglong2*>(&Bs[cur][cc][colBase + 4]);
                bp[0] = b0.x; bp[1] = b0.y; bp[2] = b1.x; bp[3] = b1.y;
            } else {
                const ull_t* pb = reinterpret_cast<const ull_t*>(&Bs[cur][cc][colBase]);
#pragma unroll
                for (int p = 0; p < TNH; p++) bp[p] = pb[p];
            }
#pragma unroll
            for (int mm = 0; mm < TM; mm++) {
                ull_t ap;
                PACK2(ap, a[mm]);
#pragma unroll
                for (int p = 0; p < TNH; p++) FMA2(acc[mm][p], ap, bp[p]);
            }
        }
        if (j + 1 < nChunks) commit(cur ^ 1);
        __syncthreads();
        cur ^= 1;
    }

    float* out = Yp + (size_t)z * M * O;
#pragma unroll
    for (int mm = 0; mm < TM; mm++) {
        int m = m0 + rowBase + mm;
        if (m < M) {
            ull_t* dst = reinterpret_cast<ull_t*>(out + (size_t)m * O + n0 + colBase);
#pragma unroll
            for (int p = 0; p < TNH; p++) dst[p] = acc[mm][p];
        }
    }
}

// ------ split-K reduce + clamp(1+x,0) + maxpool (1,2,2) + sum/sumsq ----------
// Writes PRE-BN pooled activations; BN affine is applied downstream in the
// next conv's gather (or in FC1 for the last layer).
__global__ void pool_stats_kernel(const float* __restrict__ Y, float* __restrict__ P,
                                  float* __restrict__ gsum, float* __restrict__ gsq,
                                  int B, int D, int H, int W, int O, int Hp, int Wp,
                                  int S, int sliceStride) {
    __shared__ float ssum[384];
    __shared__ float ssq[384];
    int tid = threadIdx.x;
    for (int o = tid; o < O; o += blockDim.x) { ssum[o] = 0.f; ssq[o] = 0.f; }
    __syncthreads();
    int Ne = B * D * Hp * Wp * O;
    int stride = gridDim.x * blockDim.x;
    for (int e = blockIdx.x * blockDim.x + tid; e < Ne; e += stride) {
        int o = e % O;
        int m = e / O;
        int wp = m % Wp;
        int t = m / Wp;
        int hp = t % Hp;
        t /= Hp;
        int d = t % D;
        int b = t / D;
        size_t off = ((size_t)(((b * D + d) * H + hp * 2) * W) + wp * 2) * O + o;
        float v0 = 0.f, v1 = 0.f, v2 = 0.f, v3 = 0.f;
        for (int s = 0; s < S; s++) {
            const float* src = Y + off + (size_t)s * sliceStride;
            v0 += src[0];
            v1 += src[O];
            v2 += src[(size_t)W * O];
            v3 += src[(size_t)W * O + O];
        }
        float v = fmaxf(fmaxf(v0, v1), fmaxf(v2, v3));
        v = fmaxf(1.f + v, 0.f);
        P[e] = v;
        atomicAdd(&ssum[o], v);
        atomicAdd(&ssq[o], v * v);
    }
    __syncthreads();
    for (int o = tid; o < O; o += blockDim.x) {
        atomicAdd(&gsum[o], ssum[o]);
        atomicAdd(&gsq[o], ssq[o]);
    }
}

// Computes scale/shift, then RE-ZEROES the stat buffers for the next layer
// (stream-ordered before the next pool; deterministic across graph replays).
__global__ void bn_final_kernel(float* __restrict__ sum, float* __restrict__ sq,
                                const float* __restrict__ gamma, const float* __restrict__ beta,
                                float* __restrict__ scale, float* __restrict__ shift,
                                float invN, int O) {
    int o = threadIdx.x;
    if (o < O) {
        float mean = sum[o] * invN;
        float var = sq[o] * invN - mean * mean;
        float sc = gamma[o] * rsqrtf(var + 1e-5f);
        scale[o] = sc;
        shift[o] = beta[o] - mean * sc;
    }
    if (o < 384) { sum[o] = 0.f; sq[o] = 0.f; }
}

// ---------------- FC layers --------------------------------------------------
// v: pooled L5 (pre-BN); BN affine applied inline here.
__global__ void fc1_kernel(const float* __restrict__ v, const float* __restrict__ w1,
                           const float* __restrict__ b1,
                           const float* __restrict__ scale, const float* __restrict__ shift,
                           float* __restrict__ out) {
    __shared__ float s0[256];
    __shared__ float s1[256];
    __shared__ float sSc[384];
    __shared__ float sSh[384];
    int j = blockIdx.x;
    int tid = threadIdx.x;
    for (int o = tid; o < 384; o += 256) { sSc[o] = scale[o]; sSh[o] = shift[o]; }
    __syncthreads();
    const float* wr = w1 + (size_t)j * 55296;
    float a0 = 0.f, a1 = 0.f;
    for (int k = tid; k < 55296; k += 256) {
        int o = k / 144;
        int r = k - o * 144;
        int idx = r * 384 + o;
        float sc = sSc[o], sh = sSh[o];
        float wv = wr[k];
        a0 += wv * fmaf(v[idx], sc, sh);
        a1 += wv * fmaf(v[idx + 55296], sc, sh);
    }
    s0[tid] = a0; s1[tid] = a1;
    __syncthreads();
    for (int t = 128; t > 0; t >>= 1) {
        if (tid < t) { s0[tid] += s0[tid + t]; s1[tid] += s1[tid + t]; }
        __syncthreads();
    }
    if (tid == 0) {
        out[j] = fmaxf(s0[0] + b1[j], 0.f);
        out[512 + j] = fmaxf(s1[0] + b1[j], 0.f);
    }
}

__global__ void fc2_kernel(const float* __restrict__ in, const float* __restrict__ w2,
                           const float* __restrict__ b2, float* __restrict__ out) {
    __shared__ float s0[128];
    __shared__ float s1[128];
    int i = blockIdx.x;
    int tid = threadIdx.x;
    float a0 = 0.f, a1 = 0.f;
    for (int j = tid; j < 512; j += 128) {
        float wv = w2[i * 512 + j];
        a0 += wv * in[j];
        a1 += wv * in[512 + j];
    }
    s0[tid] = a0; s1[tid] = a1;
    __syncthreads();
    for (int t = 64; t > 0; t >>= 1) {
        if (tid < t) { s0[tid] += s0[tid + t]; s1[tid] += s1[tid + t]; }
        __syncthreads();
    }
    if (tid == 0) {
        out[i] = fmaxf(s0[0] + b2[i], 0.f);
        out[256 + i] = fmaxf(s1[0] + b2[i], 0.f);
    }
}

__global__ void fc3_kernel(const float* __restrict__ in, const float* __restrict__ w3,
                           const float* __restrict__ b3, float* __restrict__ out) {
    __shared__ float s0[128];
    __shared__ float s1[128];
    int i = blockIdx.x;
    int tid = threadIdx.x;
    float a0 = 0.f, a1 = 0.f;
    for (int j = tid; j < 256; j += 128) {
        float wv = w3[i * 256 + j];
        a0 += wv * in[j];
        a1 += wv * in[256 + j];
    }
    s0[tid] = a0; s1[tid] = a1;
    __syncthreads();
    for (int t = 64; t > 0; t >>= 1) {
        if (tid < t) { s0[tid] += s0[tid + t]; s1[tid] += s1[tid + t]; }
        __syncthreads();
    }
    if (tid == 0) {
        out[i] = s0[0] + b3[i];
        out[101 + i] = s1[0] + b3[i];
    }
}

// ---------------- driver ------------------------------------------------------
extern "C" void kernel_launch(void* const* d_in, const int* in_sizes, int n_in,
                              void* d_out, int out_size) {
    const float* x = (const float*)d_in[0];
    const float* Pj[5];
    const float* Al[5];
    const float* Ga[5];
    const float* Be[5];
    for (int i = 0; i < 5; i++) {
        Pj[i] = (const float*)d_in[1 + 4 * i];
        Al[i] = (const float*)d_in[2 + 4 * i];
        Ga[i] = (const float*)d_in[3 + 4 * i];
        Be[i] = (const float*)d_in[4 + 4 * i];
    }
    const float* w1 = (const float*)d_in[21];
    const float* b1 = (const float*)d_in[22];
    const float* w2 = (const float*)d_in[23];
    const float* b2 = (const float*)d_in[24];
    const float* w3 = (const float*)d_in[25];
    const float* b3 = (const float*)d_in[26];

    float *preact, *act, *wf, *sum, *sq, *scale, *shift, *fc1b, *fc2b;
    cudaGetSymbolAddress((void**)&preact, g_preact);
    cudaGetSymbolAddress((void**)&act, g_act);
    cudaGetSymbolAddress((void**)&wf, g_wf);
    cudaGetSymbolAddress((void**)&sum, g_sum);
    cudaGetSymbolAddress((void**)&sq, g_sumsq);
    cudaGetSymbolAddress((void**)&scale, g_scale);
    cudaGetSymbolAddress((void**)&shift, g_shift);
    cudaGetSymbolAddress((void**)&fc1b, g_fc1);
    cudaGetSymbolAddress((void**)&fc2b, g_fc2);

    // input transpose to channel-last (+ upfront stats zero)
    {
        int N = 2 * 3 * 16 * 112 * 112;
        nchw2nhwc_kernel<<<(N + 255) / 256, 256>>>(x, act, sum, sq);
    }

    const int B = 2, D = 16;

    auto do_pool_bn = [&](int C_H, int C_W, int C_O, int C_S, int C_M,
                          const float* gamma, const float* beta) {
        int hp = (C_H - 2) / 2 + 1;
        int wp = (C_W - 2) / 2 + 1;
        int ne = B * D * hp * wp * C_O;
        int pb = (ne + 255) / 256;
        if (pb > 4096) pb = 4096;
        pool_stats_kernel<<<pb, 256>>>(preact, act, sum, sq, B, D, C_H, C_W, C_O, hp, wp,
                                       C_S, C_M * C_O);
        float invN = 1.f / (float)(B * D * hp * wp);
        bn_final_kernel<<<1, 384>>>(sum, sq, gamma, beta, scale, shift, invN, C_O);
    };

    // ---------------- layer 1: C=3, O=24, H=W=112 (no BN on input) ----------
    fusew_kernel<32, 2><<<dim3(2, 1), 256>>>(Pj[0], Al[0], wf, 81, 3, 24);
    conv1_kernel<<<1568, 256>>>(act, wf, preact);
    do_pool_bn(112, 112, 24, 1, 2 * 16 * 112 * 112, Ga[0], Be[0]);

    // ---------------- layer 2: C=24, O=48, H=W=56 ---------------------------
    fusew_kernel<64, 4><<<dim3((648 + 63) / 64, 1), 256>>>(Pj[1], Al[1], wf, 648, 24, 48);
    int M = 2 * 16 * 56 * 56;
    conv2_kernel<128, 48, 8, 6, 8, 24, 128, true>
        <<<dim3(M / 128, 1, 1), 128>>>(act, wf, preact, scale, shift, B, D, 56, 56, 48, 1);
    do_pool_bn(56, 56, 48, 1, M, Ga[1], Be[1]);

    // ---------------- layer 3: C=48, O=96, H=W=28, split-K=3 ----------------
    fusew2_kernel<128, 96, 8, 8, 16, 192, 2>
        <<<dim3(11, 1), 192>>>(Pj[2], Al[2], wf, 1296, 48, 96);
    M = 2 * 16 * 28 * 28;
    conv2_kernel<128, 96, 8, 8, 16, 48, 192, true>
        <<<dim3(M / 128, 1, 3), 192>>>(act, wf, preact, scale, shift, B, D, 28, 28, 96, 3);
    do_pool_bn(28, 28, 96, 3, M, Ga[2], Be[2]);

    // ---------------- layer 4: C=96, O=192, H=W=14, split-K=3 ---------------
    fusew2_kernel<128, 96, 8, 8, 16, 192, 2>
        <<<dim3(21, 2), 192>>>(Pj[3], Al[3], wf, 2592, 96, 192);
    M = 2 * 16 * 14 * 14;
    conv2_kernel<128, 96, 8, 8, 16, 96, 192, true>
        <<<dim3(M / 128, 2, 3), 192>>>(act, wf, preact, scale, shift, B, D, 14, 14, 192, 3);
    do_pool_bn(14, 14, 192, 3, M, Ga[3], Be[3]);

    // ---------------- layer 5: C=192, O=384, H=W=7, split-K=4 (R9-exact) ----
    // ONLY change vs R9: fusew2-L5 at 256t/BM128/BN128 (measured 73.1us vs 89.6us).
    fusew2_kernel<128, 128, 8, 8, 16, 256, 1>
        <<<dim3(41, 3), 256>>>(Pj[4], Al[4], wf, 5184, 192, 384);
    M = 2 * 16 * 7 * 7;
    conv2_kernel<64, 128, 8, 8, 16, 192, 128, true>
        <<<dim3((M + 63) / 64, 3, 4), 128>>>(act, wf, preact, scale, shift, B, D, 7, 7, 384, 4);
    do_pool_bn(7, 7, 384, 4, M, Ga[4], Be[4]);

    // ---------------- FC head (L5 BN fused into FC1 input) ------------------
    fc1_kernel<<<512, 256>>>(act, w1, b1, scale, shift, fc1b);
    fc2_kernel<<<256, 128>>>(fc1b, w2, b2, fc2b);
    fc3_kernel<<<101, 128>>>(fc2b, w3, b3, (float*)d_out);
}

// round 15
// speedup vs baseline: 1.1403x; 1.0195x over previous
#include <cuda_runtime.h>

typedef unsigned long long ull_t;

// ---------------- scratch (static device globals; no allocation) ------------
__device__ float g_preact[9633792];   // max partial store: L1 2*16*112*112*24
__device__ float g_act[2408448];      // max pooled/layer-input: 2*16*56*56*24
__device__ float g_wf[1990656];       // max fused weight: 5184*384
__device__ float g_sum[384];
__device__ float g_sumsq[384];
__device__ float g_scale[384];
__device__ float g_shift[384];
__device__ float g_fc1[1024];
__device__ float g_fc2[512];

#define PACK2(d, s) asm("mov.b64 %0, {%1, %1};" : "=l"(d) : "f"(s))
#define FMA2(d, a, b) asm("fma.rn.f32x2 %0, %1, %2, %0;" : "+l"(d) : "l"(a), "l"(b))

// ---------------- input transpose: (2,3,16,112,112) -> (2,16,112,112,3) -----
__global__ void nchw2nhwc_kernel(const float* __restrict__ x, float* __restrict__ out,
                                 float* __restrict__ sum, float* __restrict__ sq) {
    const int DHW = 16 * 112 * 112;
    const int N = 2 * DHW * 3;
    int e = blockIdx.x * blockDim.x + threadIdx.x;
    if (e < 384) { sum[e] = 0.f; sq[e] = 0.f; }   // upfront stats zero
    if (e >= N) return;
    int c = e % 3;
    int m = e / 3;
    int b = m / DHW;
    int r = m - b * DHW;
    out[e] = x[(b * 3 + c) * DHW + r];
}

// ---------------- small fused-weight GEMM (layers 1-2) ----------------------
// Wf[s*C+c][o] = sum_p proj[p][c*27+s] * alpha[p][o]
template <int BN, int TN>
__global__ void fusew_kernel(const float* __restrict__ proj, const float* __restrict__ alpha,
                             float* __restrict__ Wf, int K, int C, int O) {
    constexpr int BM = 64, KC = 16;
    __shared__ alignas(16) float As[KC][BM];
    __shared__ alignas(16) float Bs[KC][BN];
    const int m0 = blockIdx.x * BM;
    const int n0 = blockIdx.y * BN;
    const int tid = threadIdx.x;
    const int tm = tid >> 4;
    const int tn = tid & 15;

    float acc[4][TN];
#pragma unroll
    for (int i = 0; i < 4; i++)
#pragma unroll
        for (int j = 0; j < TN; j++) acc[i][j] = 0.f;

    for (int p0 = 0; p0 < 512; p0 += KC) {
        __syncthreads();
        for (int idx = tid; idx < KC * BM; idx += 256) {
            int pp = idx / BM, i = idx - pp * BM;
            int m = m0 + i;
            As[pp][i] = (m < K) ? proj[(p0 + pp) * K + m] : 0.f;
        }
        for (int idx = tid; idx < KC * BN; idx += 256) {
            int pp = idx / BN, j = idx - pp * BN;
            int n = n0 + j;
            Bs[pp][j] = (n < O) ? alpha[(p0 + pp) * O + n] : 0.f;
        }
        __syncthreads();
#pragma unroll
        for (int pp = 0; pp < KC; ++pp) {
            float4 a4 = *(const float4*)&As[pp][tm * 4];
            float av[4] = {a4.x, a4.y, a4.z, a4.w};
            float bv[TN];
            if constexpr (TN == 4) {
                float4 b4 = *(const float4*)&Bs[pp][tn * 4];
                bv[0] = b4.x; bv[1] = b4.y; bv[2] = b4.z; bv[3] = b4.w;
            } else {
                float2 b2 = *(const float2*)&Bs[pp][tn * 2];
                bv[0] = b2.x; bv[1] = b2.y;
            }
#pragma unroll
            for (int mm = 0; mm < 4; ++mm)
#pragma unroll
                for (int nn = 0; nn < TN; ++nn)
                    acc[mm][nn] = fmaf(av[mm], bv[nn], acc[mm][nn]);
        }
    }
#pragma unroll
    for (int mm = 0; mm < 4; ++mm) {
        int m = m0 + tm * 4 + mm;
        if (m < K) {
            int c = m / 27;
            int s = m - c * 27;
            float* dst = Wf + (s * C + c) * O + n0 + tn * TN;
#pragma unroll
            for (int nn = 0; nn < TN; ++nn) {
                int n = n0 + tn * TN + nn;
                if (n < O) dst[nn] = acc[mm][nn];
            }
        }
    }
}

// ---------------- big fused-weight GEMM (layers 3-5), FFMA2 + double buffer --
template <int BM, int BN, int TM, int TN, int KC, int THREADS, int MINB>
__global__ void __launch_bounds__(THREADS, MINB)
fusew2_kernel(const float* __restrict__ proj, const float* __restrict__ alpha,
              float* __restrict__ Wf, int K, int C, int O) {
    constexpr int NCOL = BN / TN;
    constexpr int TNH = TN / 2;
    constexpr int NCHUNK = 512 / KC;
    constexpr int A4 = BM * KC / 4;
    constexpr int NA = (A4 + THREADS - 1) / THREADS;
    constexpr int B4 = BN * KC / 4;
    constexpr int NB = (B4 + THREADS - 1) / THREADS;
    __shared__ alignas(16) float As[2][KC][BM];
    __shared__ alignas(16) float Bs[2][KC][BN];
    const int m0 = blockIdx.x * BM;
    const int n0 = blockIdx.y * BN;
    const int tid = threadIdx.x;
    const int col = tid % NCOL, row = tid / NCOL;
    const int rowBase = row * TM, colBase = col * TN;

    ull_t acc[TM][TNH];
#pragma unroll
    for (int a = 0; a < TM; a++)
#pragma unroll
        for (int b = 0; b < TNH; b++) acc[a][b] = 0ULL;

    float4 stA[NA], stB[NB];
    auto gather = [&](int j) {
        int p0 = j * KC;
#pragma unroll
        for (int t = 0; t < NA; t++) {
            int q = tid + t * THREADS;
            float4 v = make_float4(0.f, 0.f, 0.f, 0.f);
            if (A4 % THREADS == 0 || q < A4) {
                int i4 = q % (BM / 4);
                int pp = q / (BM / 4);
                int m = m0 + i4 * 4;
                if (m < K) v = *reinterpret_cast<const float4*>(proj + (size_t)(p0 + pp) * K + m);
            }
            stA[t] = v;
        }
#pragma unroll
        for (int t = 0; t < NB; t++) {
            int q = tid + t * THREADS;
            float4 v = make_float4(0.f, 0.f, 0.f, 0.f);
            if (B4 % THREADS == 0 || q < B4) {
                int cc = q / (BN / 4);
                int c4 = q % (BN / 4);
                v = *reinterpret_cast<const float4*>(alpha + (size_t)(p0 + cc) * O + n0 + c4 * 4);
            }
            stB[t] = v;
        }
    };
    auto commit = [&](int buf) {
#pragma unroll
        for (int t = 0; t < NA; t++) {
            int q = tid + t * THREADS;
            if (A4 % THREADS == 0 || q < A4) {
                int i4 = q % (BM / 4);
                int pp = q / (BM / 4);
                *reinterpret_cast<float4*>(&As[buf][pp][i4 * 4]) = stA[t];
            }
        }
#pragma unroll
        for (int t = 0; t < NB; t++) {
            int q = tid + t * THREADS;
            if (B4 % THREADS == 0 || q < B4) {
                int cc = q / (BN / 4);
                int c4 = q % (BN / 4);
                *reinterpret_cast<float4*>(&Bs[buf][cc][c4 * 4]) = stB[t];
            }
        }
    };

    gather(0);
    commit(0);
    __syncthreads();
    int cur = 0;
    for (int j = 0; j < NCHUNK; ++j) {
        if (j + 1 < NCHUNK) gather(j + 1);
#pragma unroll
        for (int cc = 0; cc < KC; ++cc) {
            float a[TM];
#pragma unroll
            for (int f = 0; f < TM; f += 4)
                *reinterpret_cast<float4*>(&a[f]) =
                    *reinterpret_cast<const float4*>(&As[cur][cc][rowBase + f]);
            ull_t bp[TNH];
            ulonglong2 b0 = *reinterpret_cast<const ulonglong2*>(&Bs[cur][cc][colBase]);
            ulonglong2 b1 = *reinterpret_cast<const ulonglong2*>(&Bs[cur][cc][colBase + 4]);
            bp[0] = b0.x; bp[1] = b0.y; bp[2] = b1.x; bp[3] = b1.y;
#pragma unroll
            for (int mm = 0; mm < TM; mm++) {
                ull_t ap;
                PACK2(ap, a[mm]);
#pragma unroll
                for (int p = 0; p < TNH; p++) FMA2(acc[mm][p], ap, bp[p]);
            }
        }
        if (j + 1 < NCHUNK) commit(cur ^ 1);
        __syncthreads();
        cur ^= 1;
    }

#pragma unroll
    for (int mm = 0; mm < TM; mm++) {
        int m = m0 + rowBase + mm;
        if (m < K) {
            int c = m / 27;
            int s = m - c * 27;
            ull_t* dst = reinterpret_cast<ull_t*>(Wf + ((size_t)(s * C + c)) * O + n0 + colBase);
#pragma unroll
            for (int p = 0; p < TNH; p++) dst[p] = acc[mm][p];
        }
    }
}

// ---------------- layer-1 direct conv (C=3, O=24), writes RAW sums ----------
__global__ void conv1_kernel(const float* __restrict__ X, const float* __restrict__ Wf,
                             float* __restrict__ Y) {
    __shared__ alignas(16) float sW[81 * 24];
    for (int i = threadIdx.x; i < 81 * 24; i += 256) sW[i] = Wf[i];
    __syncthreads();
    int m = blockIdx.x * 256 + threadIdx.x;  // M = 401408 exact
    int w = m % 112;
    int t = m / 112;
    int h = t % 112;
    t /= 112;
    int d = t % 16;
    ull_t acc[12];
#pragma unroll
    for (int p = 0; p < 12; p++) acc[p] = 0ULL;
    const float* base = X + (size_t)m * 3;
#pragma unroll
    for (int s = 0; s < 27; s++) {
        const int dz = s / 9 - 1, dy = (s / 3) % 3 - 1, dx = s % 3 - 1;
        int dd = d + dz, hh = h + dy, ww = w + dx;
        float x0 = 0.f, x1 = 0.f, x2 = 0.f;
        if ((unsigned)dd < 16u && (unsigned)hh < 112u && (unsigned)ww < 112u) {
            const float* px = base + ((dz * 112 + dy) * 112 + dx) * 3;
            x0 = px[0]; x1 = px[1]; x2 = px[2];
        }
        float xv[3] = {x0, x1, x2};
#pragma unroll
        for (int c = 0; c < 3; c++) {
            ull_t xp;
            PACK2(xp, xv[c]);
            const ulonglong2* wr = reinterpret_cast<const ulonglong2*>(&sW[(s * 3 + c) * 24]);
#pragma unroll
            for (int p2 = 0; p2 < 6; p2++) {
                ulonglong2 wv = wr[p2];
                FMA2(acc[2 * p2], xp, wv.x);
                FMA2(acc[2 * p2 + 1], xp, wv.y);
            }
        }
    }
    ull_t* dst = reinterpret_cast<ull_t*>(Y + (size_t)m * 24);
#pragma unroll
    for (int p = 0; p < 12; p++) dst[p] = acc[p];
}

// ---------------- implicit-GEMM conv: FFMA2, double buffer, split-K ----------
// BN of the PREVIOUS layer fused into the A-gather (x*scale[c]+shift[c],
// zeros stay zero for padding — matches reference BN-then-pad order).
// X: [B,D,H,W,C], Wf: [27*C][O] (row = s*C+c), Yp: S partial slices (RAW sums)
template <int BM, int BN, int TM, int TN, int KC, int C, int THREADS, bool BNIN>
__global__ void __launch_bounds__(THREADS, 2)
conv2_kernel(const float* __restrict__ X, const float* __restrict__ Wf,
             float* __restrict__ Yp, const float* __restrict__ scl,
             const float* __restrict__ shf,
             int B_, int D, int H, int W, int O, int S) {
    constexpr int NCOL = BN / TN;
    constexpr int CPT = C / KC;
    constexpr int TNH = TN / 2;
    constexpr int A4 = BM * KC / 4;
    constexpr int NA = (A4 + THREADS - 1) / THREADS;
    constexpr int B4 = BN * KC / 4;
    constexpr int NB = (B4 + THREADS - 1) / THREADS;
    __shared__ alignas(16) float As[2][KC][BM];
    __shared__ alignas(16) float Bs[2][KC][BN];
    __shared__ int sBase[BM];
    __shared__ int sDHW[BM];
    __shared__ alignas(16) float sScale[BNIN ? C : 4];
    __shared__ alignas(16) float sShift[BNIN ? C : 4];
    const int M = B_ * D * H * W;
    const int m0 = blockIdx.x * BM;
    const int n0 = blockIdx.y * BN;
    const int z = blockIdx.z;
    const int s0 = (27 * z) / S, s1 = (27 * (z + 1)) / S;
    const int nChunks = (s1 - s0) * CPT;
    const int tid = threadIdx.x;
    const int col = tid % NCOL, row = tid / NCOL;
    const int rowBase = row * TM, colBase = col * TN;

    if constexpr (BNIN) {
        for (int i = tid; i < C; i += THREADS) {
            sScale[i] = scl[i];
            sShift[i] = shf[i];
        }
    }
    for (int i = tid; i < BM; i += THREADS) {
        int m = m0 + i;
        if (m < M) {
            int w = m % W;
            int t = m / W;
            int h = t % H;
            t /= H;
            int d = t % D;
            sBase[i] = m * C;
            sDHW[i] = (d << 20) | (h << 10) | w;
        } else {
            sBase[i] = -1;
            sDHW[i] = 0;
        }
    }
    __syncthreads();

    ull_t acc[TM][TNH];
#pragma unroll
    for (int a = 0; a < TM; a++)
#pragma unroll
        for (int b = 0; b < TNH; b++) acc[a][b] = 0ULL;

    float4 stA[NA], stB[NB];
    auto gather = [&](int j) {
        int s = s0 + j / CPT;
        int c0 = (j % CPT) * KC;
        int dz = s / 9 - 1, dy = (s / 3) % 3 - 1, dx = s % 3 - 1;
        int koff = ((dz * H + dy) * W + dx) * C + c0;
#pragma unroll
        for (int t = 0; t < NA; t++) {
            int q = tid + t * THREADS;
            float4 v = make_float4(0.f, 0.f, 0.f, 0.f);
            if (A4 % THREADS == 0 || q < A4) {
                int i = q % BM;
                int cc4 = q / BM;
                int bs = sBase[i];
                if (bs >= 0) {
                    int dhw = sDHW[i];
                    int dd = (dhw >> 20) + dz;
                    int hh = ((dhw >> 10) & 1023) + dy;
                    int ww = (dhw & 1023) + dx;
                    if ((unsigned)dd < (unsigned)D && (unsigned)hh < (unsigned)H &&
                        (unsigned)ww < (unsigned)W) {
                        v = *reinterpret_cast<const float4*>(X + bs + koff + cc4 * 4);
                        if constexpr (BNIN) {
                            int ch = c0 + cc4 * 4;
                            float4 sc = *reinterpret_cast<const float4*>(&sScale[ch]);
                            float4 sh = *reinterpret_cast<const float4*>(&sShift[ch]);
                            v.x = fmaf(v.x, sc.x, sh.x);
                            v.y = fmaf(v.y, sc.y, sh.y);
                            v.z = fmaf(v.z, sc.z, sh.z);
                            v.w = fmaf(v.w, sc.w, sh.w);
                        }
                    }
                }
            }
            stA[t] = v;
        }
        const float* wb = Wf + ((size_t)(s * C + c0)) * O + n0;
#pragma unroll
        for (int t = 0; t < NB; t++) {
            int q = tid + t * THREADS;
            float4 v = make_float4(0.f, 0.f, 0.f, 0.f);
            if (B4 % THREADS == 0 || q < B4) {
                int cc = q / (BN / 4);
                int c4 = q % (BN / 4);
                v = *reinterpret_cast<const float4*>(wb + (size_t)cc * O + c4 * 4);
            }
            stB[t] = v;
        }
    };
    auto commit = [&](int buf) {
#pragma unroll
        for (int t = 0; t < NA; t++) {
            int q = tid + t * THREADS;
            if (A4 % THREADS == 0 || q < A4) {
                int i = q % BM;
                int cc = (q / BM) * 4;
                As[buf][cc + 0][i] = stA[t].x;
                As[buf][cc + 1][i] = stA[t].y;
                As[buf][cc + 2][i] = stA[t].z;
                As[buf][cc + 3][i] = stA[t].w;
            }
        }
#pragma unroll
        for (int t = 0; t < NB; t++) {
            int q = tid + t * THREADS;
            if (B4 % THREADS == 0 || q < B4) {
                int cc = q / (BN / 4);
                int c4 = q % (BN / 4);
                *reinterpret_cast<float4*>(&Bs[buf][cc][c4 * 4]) = stB[t];
            }
        }
    };

    gather(0);
    commit(0);
    __syncthreads();
    int cur = 0;
    for (int j = 0; j < nChunks; ++j) {
        if (j + 1 < nChunks) gather(j + 1);
#pragma unroll
        for (int cc = 0; cc < KC; ++cc) {
            float a[TM];
            *reinterpret_cast<float4*>(&a[0]) = *reinterpret_cast<const float4*>(&As[cur][cc][rowBase]);
            *reinterpret_cast<float4*>(&a[4]) = *reinterpret_cast<const float4*>(&As[cur][cc][rowBase + 4]);
            ull_t bp[TNH];
            if constexpr (TN == 8) {
                ulonglong2 b0 = *reinterpret_cast<const ulonglong2*>(&Bs[cur][cc][colBase]);
                ulonglong2 b1 = *reinterpret_cast<const ulonglong2*>(&Bs[cur][cc][colBase + 4]);
                bp[0] = b0.x; bp[1] = b0.y; bp[2] = b1.x; bp[3] = b1.y;
            } else {
                const ull_t* pb = reinterpret_cast<const ull_t*>(&Bs[cur][cc][colBase]);
#pragma unroll
                for (int p = 0; p < TNH; p++) bp[p] = pb[p];
            }
#pragma unroll
            for (int mm = 0; mm < TM; mm++) {
                ull_t ap;
                PACK2(ap, a[mm]);
#pragma unroll
                for (int p = 0; p < TNH; p++) FMA2(acc[mm][p], ap, bp[p]);
            }
        }
        if (j + 1 < nChunks) commit(cur ^ 1);
        __syncthreads();
        cur ^= 1;
    }

    float* out = Yp + (size_t)z * M * O;
#pragma unroll
    for (int mm = 0; mm < TM; mm++) {
        int m = m0 + rowBase + mm;
        if (m < M) {
            ull_t* dst = reinterpret_cast<ull_t*>(out + (size_t)m * O + n0 + colBase);
#pragma unroll
            for (int p = 0; p < TNH; p++) dst[p] = acc[mm][p];
        }
    }
}

// ------ split-K reduce + clamp(1+x,0) + maxpool (1,2,2) + sum/sumsq ----------
// Channel-major thread mapping: o = g % O is FIXED per thread (launch ensures
// NT % O == 0), spatial strides by NT/O. Stats accumulate in 2 registers;
// exactly 2 shared atomics per THREAD (vs 2 per element before). Coalescing
// unchanged (adjacent threads = adjacent channels at the same pixel).
// Writes PRE-BN pooled activations.
__global__ void pool_stats_kernel(const float* __restrict__ Y, float* __restrict__ P,
                                  float* __restrict__ gsum, float* __restrict__ gsq,
                                  int B, int D, int H, int W, int O, int Hp, int Wp,
                                  int S, int sliceStride) {
    __shared__ float ssum[384];
    __shared__ float ssq[384];
    int tid = threadIdx.x;
    for (int o = tid; o < O; o += blockDim.x) { ssum[o] = 0.f; ssq[o] = 0.f; }
    __syncthreads();
    const int NT = gridDim.x * blockDim.x;     // launch guarantees NT % O == 0
    const int g = blockIdx.x * blockDim.x + tid;
    const int o = g % O;                       // constant across the loop
    const int sp0 = g / O;
    const int spStride = NT / O;
    const int NSP = B * D * Hp * Wp;
    float rs = 0.f, rq = 0.f;
    for (int sp = sp0; sp < NSP; sp += spStride) {
        int wp = sp % Wp;
        int t = sp / Wp;
        int hp = t % Hp;
        t /= Hp;
        int d = t % D;
        int b = t / D;
        size_t off = ((size_t)(((b * D + d) * H + hp * 2) * W) + wp * 2) * O + o;
        float v0 = 0.f, v1 = 0.f, v2 = 0.f, v3 = 0.f;
        for (int s = 0; s < S; s++) {
            const float* src = Y + off + (size_t)s * sliceStride;
            v0 += src[0];
            v1 += src[O];
            v2 += src[(size_t)W * O];
            v3 += src[(size_t)W * O + O];
        }
        float v = fmaxf(fmaxf(v0, v1), fmaxf(v2, v3));
        v = fmaxf(1.f + v, 0.f);
        P[(size_t)sp * O + o] = v;
        rs += v;
        rq += v * v;
    }
    atomicAdd(&ssum[o], rs);
    atomicAdd(&ssq[o], rq);
    __syncthreads();
    for (int oo = tid; oo < O; oo += blockDim.x) {
        atomicAdd(&gsum[oo], ssum[oo]);
        atomicAdd(&gsq[oo], ssq[oo]);
    }
}

// Computes scale/shift, then RE-ZEROES the stat buffers for the next layer
// (stream-ordered before the next pool; deterministic across graph replays).
__global__ void bn_final_kernel(float* __restrict__ sum, float* __restrict__ sq,
                                const float* __restrict__ gamma, const float* __restrict__ beta,
                                float* __restrict__ scale, float* __restrict__ shift,
                                float invN, int O) {
    int o = threadIdx.x;
    if (o < O) {
        float mean = sum[o] * invN;
        float var = sq[o] * invN - mean * mean;
        float sc = gamma[o] * rsqrtf(var + 1e-5f);
        scale[o] = sc;
        shift[o] = beta[o] - mean * sc;
    }
    if (o < 384) { sum[o] = 0.f; sq[o] = 0.f; }
}

// ---------------- FC layers --------------------------------------------------
// v: pooled L5 (pre-BN); BN affine applied inline here.
__global__ void fc1_kernel(const float* __restrict__ v, const float* __restrict__ w1,
                           const float* __restrict__ b1,
                           const float* __restrict__ scale, const float* __restrict__ shift,
                           float* __restrict__ out) {
    __shared__ float s0[256];
    __shared__ float s1[256];
    __shared__ float sSc[384];
    __shared__ float sSh[384];
    int j = blockIdx.x;
    int tid = threadIdx.x;
    for (int o = tid; o < 384; o += 256) { sSc[o] = scale[o]; sSh[o] = shift[o]; }
    __syncthreads();
    const float* wr = w1 + (size_t)j * 55296;
    float a0 = 0.f, a1 = 0.f;
    for (int k = tid; k < 55296; k += 256) {
        int o = k / 144;
        int r = k - o * 144;
        int idx = r * 384 + o;
        float sc = sSc[o], sh = sSh[o];
        float wv = wr[k];
        a0 += wv * fmaf(v[idx], sc, sh);
        a1 += wv * fmaf(v[idx + 55296], sc, sh);
    }
    s0[tid] = a0; s1[tid] = a1;
    __syncthreads();
    for (int t = 128; t > 0; t >>= 1) {
        if (tid < t) { s0[tid] += s0[tid + t]; s1[tid] += s1[tid + t]; }
        __syncthreads();
    }
    if (tid == 0) {
        out[j] = fmaxf(s0[0] + b1[j], 0.f);
        out[512 + j] = fmaxf(s1[0] + b1[j], 0.f);
    }
}

__global__ void fc2_kernel(const float* __restrict__ in, const float* __restrict__ w2,
                           const float* __restrict__ b2, float* __restrict__ out) {
    __shared__ float s0[128];
    __shared__ float s1[128];
    int i = blockIdx.x;
    int tid = threadIdx.x;
    float a0 = 0.f, a1 = 0.f;
    for (int j = tid; j < 512; j += 128) {
        float wv = w2[i * 512 + j];
        a0 += wv * in[j];
        a1 += wv * in[512 + j];
    }
    s0[tid] = a0; s1[tid] = a1;
    __syncthreads();
    for (int t = 64; t > 0; t >>= 1) {
        if (tid < t) { s0[tid] += s0[tid + t]; s1[tid] += s1[tid + t]; }
        __syncthreads();
    }
    if (tid == 0) {
        out[i] = fmaxf(s0[0] + b2[i], 0.f);
        out[256 + i] = fmaxf(s1[0] + b2[i], 0.f);
    }
}

__global__ void fc3_kernel(const float* __restrict__ in, const float* __restrict__ w3,
                           const float* __restrict__ b3, float* __restrict__ out) {
    __shared__ float s0[128];
    __shared__ float s1[128];
    int i = blockIdx.x;
    int tid = threadIdx.x;
    float a0 = 0.f, a1 = 0.f;
    for (int j = tid; j < 256; j += 128) {
        float wv = w3[i * 256 + j];
        a0 += wv * in[j];
        a1 += wv * in[256 + j];
    }
    s0[tid] = a0; s1[tid] = a1;
    __syncthreads();
    for (int t = 64; t > 0; t >>= 1) {
        if (tid < t) { s0[tid] += s0[tid + t]; s1[tid] += s1[tid + t]; }
        __syncthreads();
    }
    if (tid == 0) {
        out[i] = s0[0] + b3[i];
        out[101 + i] = s1[0] + b3[i];
    }
}

// ---------------- driver ------------------------------------------------------
extern "C" void kernel_launch(void* const* d_in, const int* in_sizes, int n_in,
                              void* d_out, int out_size) {
    const float* x = (const float*)d_in[0];
    const float* Pj[5];
    const float* Al[5];
    const float* Ga[5];
    const float* Be[5];
    for (int i = 0; i < 5; i++) {
        Pj[i] = (const float*)d_in[1 + 4 * i];
        Al[i] = (const float*)d_in[2 + 4 * i];
        Ga[i] = (const float*)d_in[3 + 4 * i];
        Be[i] = (const float*)d_in[4 + 4 * i];
    }
    const float* w1 = (const float*)d_in[21];
    const float* b1 = (const float*)d_in[22];
    const float* w2 = (const float*)d_in[23];
    const float* b2 = (const float*)d_in[24];
    const float* w3 = (const float*)d_in[25];
    const float* b3 = (const float*)d_in[26];

    float *preact, *act, *wf, *sum, *sq, *scale, *shift, *fc1b, *fc2b;
    cudaGetSymbolAddress((void**)&preact, g_preact);
    cudaGetSymbolAddress((void**)&act, g_act);
    cudaGetSymbolAddress((void**)&wf, g_wf);
    cudaGetSymbolAddress((void**)&sum, g_sum);
    cudaGetSymbolAddress((void**)&sq, g_sumsq);
    cudaGetSymbolAddress((void**)&scale, g_scale);
    cudaGetSymbolAddress((void**)&shift, g_shift);
    cudaGetSymbolAddress((void**)&fc1b, g_fc1);
    cudaGetSymbolAddress((void**)&fc2b, g_fc2);

    // input transpose to channel-last (+ upfront stats zero)
    {
        int N = 2 * 3 * 16 * 112 * 112;
        nchw2nhwc_kernel<<<(N + 255) / 256, 256>>>(x, act, sum, sq);
    }

    const int B = 2, D = 16;

    auto do_pool_bn = [&](int C_H, int C_W, int C_O, int C_S, int C_M,
                          const float* gamma, const float* beta) {
        int hp = (C_H - 2) / 2 + 1;
        int wp = (C_W - 2) / 2 + 1;
        int ne = B * D * hp * wp * C_O;
        // blocks multiple of 3 (256*3=768 divisible by all O) -> NT % O == 0;
        // sized for ~4-8 spatial elements per thread, capped at 1536.
        int pb = (ne / 256 + 23) / 24 * 3;
        if (pb < 3) pb = 3;
        if (pb > 1536) pb = 1536;
        pool_stats_kernel<<<pb, 256>>>(preact, act, sum, sq, B, D, C_H, C_W, C_O, hp, wp,
                                       C_S, C_M * C_O);
        float invN = 1.f / (float)(B * D * hp * wp);
        bn_final_kernel<<<1, 384>>>(sum, sq, gamma, beta, scale, shift, invN, C_O);
    };

    // ---------------- layer 1: C=3, O=24, H=W=112 (no BN on input) ----------
    fusew_kernel<32, 2><<<dim3(2, 1), 256>>>(Pj[0], Al[0], wf, 81, 3, 24);
    conv1_kernel<<<1568, 256>>>(act, wf, preact);
    do_pool_bn(112, 112, 24, 1, 2 * 16 * 112 * 112, Ga[0], Be[0]);

    // ---------------- layer 2: C=24, O=48, H=W=56 ---------------------------
    fusew_kernel<64, 4><<<dim3((648 + 63) / 64, 1), 256>>>(Pj[1], Al[1], wf, 648, 24, 48);
    int M = 2 * 16 * 56 * 56;
    conv2_kernel<128, 48, 8, 6, 8, 24, 128, true>
        <<<dim3(M / 128, 1, 1), 128>>>(act, wf, preact, scale, shift, B, D, 56, 56, 48, 1);
    do_pool_bn(56, 56, 48, 1, M, Ga[1], Be[1]);

    // ---------------- layer 3: C=48, O=96, H=W=28, split-K=3 ----------------
    fusew2_kernel<128, 96, 8, 8, 16, 192, 2>
        <<<dim3(11, 1), 192>>>(Pj[2], Al[2], wf, 1296, 48, 96);
    M = 2 * 16 * 28 * 28;
    conv2_kernel<128, 96, 8, 8, 16, 48, 192, true>
        <<<dim3(M / 128, 1, 3), 192>>>(act, wf, preact, scale, shift, B, D, 28, 28, 96, 3);
    do_pool_bn(28, 28, 96, 3, M, Ga[2], Be[2]);

    // ---------------- layer 4: C=96, O=192, H=W=14, split-K=3 ---------------
    fusew2_kernel<128, 96, 8, 8, 16, 192, 2>
        <<<dim3(21, 2), 192>>>(Pj[3], Al[3], wf, 2592, 96, 192);
    M = 2 * 16 * 14 * 14;
    conv2_kernel<128, 96, 8, 8, 16, 96, 192, true>
        <<<dim3(M / 128, 2, 3), 192>>>(act, wf, preact, scale, shift, B, D, 14, 14, 192, 3);
    do_pool_bn(14, 14, 192, 3, M, Ga[3], Be[3]);

    // ---------------- layer 5: C=192, O=384, H=W=7, split-K=4 ---------------
    fusew2_kernel<128, 128, 8, 8, 16, 256, 1>
        <<<dim3(41, 3), 256>>>(Pj[4], Al[4], wf, 5184, 192, 384);
    M = 2 * 16 * 7 * 7;
    conv2_kernel<64, 128, 8, 8, 16, 192, 128, true>
        <<<dim3((M + 63) / 64, 3, 4), 128>>>(act, wf, preact, scale, shift, B, D, 7, 7, 384, 4);
    do_pool_bn(7, 7, 384, 4, M, Ga[4], Be[4]);

    // ---------------- FC head (L5 BN fused into FC1 input) ------------------
    fc1_kernel<<<512, 256>>>(act, w1, b1, scale, shift, fc1b);
    fc2_kernel<<<256, 128>>>(fc1b, w2, b2, fc2b);
    fc3_kernel<<<101, 128>>>(fc2b, w3, b3, (float*)d_out);
}

// round 16
// speedup vs baseline: 1.1406x; 1.0002x over previous
#include <cuda_runtime.h>

typedef unsigned long long ull_t;

// ---------------- scratch (static device globals; no allocation) ------------
__device__ float g_preact[9633792];   // max partial store: L1 2*16*112*112*24
__device__ float g_act[2408448];      // max pooled/layer-input: 2*16*56*56*24
__device__ float g_wf[1990656];       // max fused weight: 5184*384
__device__ float g_sum[384];
__device__ float g_sumsq[384];
__device__ float g_scale[384];
__device__ float g_shift[384];
__device__ float g_fc1[1024];
__device__ float g_fc2[512];

#define PACK2(d, s) asm("mov.b64 %0, {%1, %1};" : "=l"(d) : "f"(s))
#define FMA2(d, a, b) asm("fma.rn.f32x2 %0, %1, %2, %0;" : "+l"(d) : "l"(a), "l"(b))

// ---------------- input transpose: (2,3,16,112,112) -> (2,16,112,112,3) -----
__global__ void nchw2nhwc_kernel(const float* __restrict__ x, float* __restrict__ out,
                                 float* __restrict__ sum, float* __restrict__ sq) {
    const int DHW = 16 * 112 * 112;
    const int N = 2 * DHW * 3;
    int e = blockIdx.x * blockDim.x + threadIdx.x;
    if (e < 384) { sum[e] = 0.f; sq[e] = 0.f; }   // upfront stats zero
    if (e >= N) return;
    int c = e % 3;
    int m = e / 3;
    int b = m / DHW;
    int r = m - b * DHW;
    out[e] = x[(b * 3 + c) * DHW + r];
}

// ---------------- small fused-weight GEMM (layers 1-2) ----------------------
// Wf[s*C+c][o] = sum_p proj[p][c*27+s] * alpha[p][o]
template <int BN, int TN>
__global__ void fusew_kernel(const float* __restrict__ proj, const float* __restrict__ alpha,
                             float* __restrict__ Wf, int K, int C, int O) {
    constexpr int BM = 64, KC = 16;
    __shared__ alignas(16) float As[KC][BM];
    __shared__ alignas(16) float Bs[KC][BN];
    const int m0 = blockIdx.x * BM;
    const int n0 = blockIdx.y * BN;
    const int tid = threadIdx.x;
    const int tm = tid >> 4;
    const int tn = tid & 15;

    float acc[4][TN];
#pragma unroll
    for (int i = 0; i < 4; i++)
#pragma unroll
        for (int j = 0; j < TN; j++) acc[i][j] = 0.f;

    for (int p0 = 0; p0 < 512; p0 += KC) {
        __syncthreads();
        for (int idx = tid; idx < KC * BM; idx += 256) {
            int pp = idx / BM, i = idx - pp * BM;
            int m = m0 + i;
            As[pp][i] = (m < K) ? proj[(p0 + pp) * K + m] : 0.f;
        }
        for (int idx = tid; idx < KC * BN; idx += 256) {
            int pp = idx / BN, j = idx - pp * BN;
            int n = n0 + j;
            Bs[pp][j] = (n < O) ? alpha[(p0 + pp) * O + n] : 0.f;
        }
        __syncthreads();
#pragma unroll
        for (int pp = 0; pp < KC; ++pp) {
            float4 a4 = *(const float4*)&As[pp][tm * 4];
            float av[4] = {a4.x, a4.y, a4.z, a4.w};
            float bv[TN];
            if constexpr (TN == 4) {
                float4 b4 = *(const float4*)&Bs[pp][tn * 4];
                bv[0] = b4.x; bv[1] = b4.y; bv[2] = b4.z; bv[3] = b4.w;
            } else {
                float2 b2 = *(const float2*)&Bs[pp][tn * 2];
                bv[0] = b2.x; bv[1] = b2.y;
            }
#pragma unroll
            for (int mm = 0; mm < 4; ++mm)
#pragma unroll
                for (int nn = 0; nn < TN; ++nn)
                    acc[mm][nn] = fmaf(av[mm], bv[nn], acc[mm][nn]);
        }
    }
#pragma unroll
    for (int mm = 0; mm < 4; ++mm) {
        int m = m0 + tm * 4 + mm;
        if (m < K) {
            int c = m / 27;
            int s = m - c * 27;
            float* dst = Wf + (s * C + c) * O + n0 + tn * TN;
#pragma unroll
            for (int nn = 0; nn < TN; ++nn) {
                int n = n0 + tn * TN + nn;
                if (n < O) dst[nn] = acc[mm][nn];
            }
        }
    }
}

// ---------------- big fused-weight GEMM (layers 3-5), FFMA2 + double buffer --
template <int BM, int BN, int TM, int TN, int KC, int THREADS, int MINB>
__global__ void __launch_bounds__(THREADS, MINB)
fusew2_kernel(const float* __restrict__ proj, const float* __restrict__ alpha,
              float* __restrict__ Wf, int K, int C, int O) {
    constexpr int NCOL = BN / TN;
    constexpr int TNH = TN / 2;
    constexpr int NCHUNK = 512 / KC;
    constexpr int A4 = BM * KC / 4;
    constexpr int NA = (A4 + THREADS - 1) / THREADS;
    constexpr int B4 = BN * KC / 4;
    constexpr int NB = (B4 + THREADS - 1) / THREADS;
    __shared__ alignas(16) float As[2][KC][BM];
    __shared__ alignas(16) float Bs[2][KC][BN];
    const int m0 = blockIdx.x * BM;
    const int n0 = blockIdx.y * BN;
    const int tid = threadIdx.x;
    const int col = tid % NCOL, row = tid / NCOL;
    const int rowBase = row * TM, colBase = col * TN;

    ull_t acc[TM][TNH];
#pragma unroll
    for (int a = 0; a < TM; a++)
#pragma unroll
        for (int b = 0; b < TNH; b++) acc[a][b] = 0ULL;

    float4 stA[NA], stB[NB];
    auto gather = [&](int j) {
        int p0 = j * KC;
#pragma unroll
        for (int t = 0; t < NA; t++) {
            int q = tid + t * THREADS;
            float4 v = make_float4(0.f, 0.f, 0.f, 0.f);
            if (A4 % THREADS == 0 || q < A4) {
                int i4 = q % (BM / 4);
                int pp = q / (BM / 4);
                int m = m0 + i4 * 4;
                if (m < K) v = *reinterpret_cast<const float4*>(proj + (size_t)(p0 + pp) * K + m);
            }
            stA[t] = v;
        }
#pragma unroll
        for (int t = 0; t < NB; t++) {
            int q = tid + t * THREADS;
            float4 v = make_float4(0.f, 0.f, 0.f, 0.f);
            if (B4 % THREADS == 0 || q < B4) {
                int cc = q / (BN / 4);
                int c4 = q % (BN / 4);
                v = *reinterpret_cast<const float4*>(alpha + (size_t)(p0 + cc) * O + n0 + c4 * 4);
            }
            stB[t] = v;
        }
    };
    auto commit = [&](int buf) {
#pragma unroll
        for (int t = 0; t < NA; t++) {
            int q = tid + t * THREADS;
            if (A4 % THREADS == 0 || q < A4) {
                int i4 = q % (BM / 4);
                int pp = q / (BM / 4);
                *reinterpret_cast<float4*>(&As[buf][pp][i4 * 4]) = stA[t];
            }
        }
#pragma unroll
        for (int t = 0; t < NB; t++) {
            int q = tid + t * THREADS;
            if (B4 % THREADS == 0 || q < B4) {
                int cc = q / (BN / 4);
                int c4 = q % (BN / 4);
                *reinterpret_cast<float4*>(&Bs[buf][cc][c4 * 4]) = stB[t];
            }
        }
    };

    gather(0);
    commit(0);
    __syncthreads();
    int cur = 0;
    for (int j = 0; j < NCHUNK; ++j) {
        if (j + 1 < NCHUNK) gather(j + 1);
#pragma unroll
        for (int cc = 0; cc < KC; ++cc) {
            float a[TM];
#pragma unroll
            for (int f = 0; f < TM; f += 4)
                *reinterpret_cast<float4*>(&a[f]) =
                    *reinterpret_cast<const float4*>(&As[cur][cc][rowBase + f]);
            ull_t bp[TNH];
            ulonglong2 b0 = *reinterpret_cast<const ulonglong2*>(&Bs[cur][cc][colBase]);
            ulonglong2 b1 = *reinterpret_cast<const ulonglong2*>(&Bs[cur][cc][colBase + 4]);
            bp[0] = b0.x; bp[1] = b0.y; bp[2] = b1.x; bp[3] = b1.y;
#pragma unroll
            for (int mm = 0; mm < TM; mm++) {
                ull_t ap;
                PACK2(ap, a[mm]);
#pragma unroll
                for (int p = 0; p < TNH; p++) FMA2(acc[mm][p], ap, bp[p]);
            }
        }
        if (j + 1 < NCHUNK) commit(cur ^ 1);
        __syncthreads();
        cur ^= 1;
    }

#pragma unroll
    for (int mm = 0; mm < TM; mm++) {
        int m = m0 + rowBase + mm;
        if (m < K) {
            int c = m / 27;
            int s = m - c * 27;
            ull_t* dst = reinterpret_cast<ull_t*>(Wf + ((size_t)(s * C + c)) * O + n0 + colBase);
#pragma unroll
            for (int p = 0; p < TNH; p++) dst[p] = acc[mm][p];
        }
    }
}

// ---------------- layer-1 direct conv (C=3, O=24), writes RAW sums ----------
__global__ void conv1_kernel(const float* __restrict__ X, const float* __restrict__ Wf,
                             float* __restrict__ Y) {
    __shared__ alignas(16) float sW[81 * 24];
    for (int i = threadIdx.x; i < 81 * 24; i += 256) sW[i] = Wf[i];
    __syncthreads();
    int m = blockIdx.x * 256 + threadIdx.x;  // M = 401408 exact
    int w = m % 112;
    int t = m / 112;
    int h = t % 112;
    t /= 112;
    int d = t % 16;
    ull_t acc[12];
#pragma unroll
    for (int p = 0; p < 12; p++) acc[p] = 0ULL;
    const float* base = X + (size_t)m * 3;
#pragma unroll
    for (int s = 0; s < 27; s++) {
        const int dz = s / 9 - 1, dy = (s / 3) % 3 - 1, dx = s % 3 - 1;
        int dd = d + dz, hh = h + dy, ww = w + dx;
        float x0 = 0.f, x1 = 0.f, x2 = 0.f;
        if ((unsigned)dd < 16u && (unsigned)hh < 112u && (unsigned)ww < 112u) {
            const float* px = base + ((dz * 112 + dy) * 112 + dx) * 3;
            x0 = px[0]; x1 = px[1]; x2 = px[2];
        }
        float xv[3] = {x0, x1, x2};
#pragma unroll
        for (int c = 0; c < 3; c++) {
            ull_t xp;
            PACK2(xp, xv[c]);
            const ulonglong2* wr = reinterpret_cast<const ulonglong2*>(&sW[(s * 3 + c) * 24]);
#pragma unroll
            for (int p2 = 0; p2 < 6; p2++) {
                ulonglong2 wv = wr[p2];
                FMA2(acc[2 * p2], xp, wv.x);
                FMA2(acc[2 * p2 + 1], xp, wv.y);
            }
        }
    }
    ull_t* dst = reinterpret_cast<ull_t*>(Y + (size_t)m * 24);
#pragma unroll
    for (int p = 0; p < 12; p++) dst[p] = acc[p];
}

// ---------------- implicit-GEMM conv: FFMA2, double buffer, split-K ----------
// BN of the PREVIOUS layer fused into the A-gather (x*scale[c]+shift[c],
// zeros stay zero for padding — matches reference BN-then-pad order).
// X: [B,D,H,W,C], Wf: [27*C][O] (row = s*C+c), Yp: S partial slices (RAW sums)
template <int BM, int BN, int TM, int TN, int KC, int C, int THREADS, bool BNIN>
__global__ void __launch_bounds__(THREADS, 2)
conv2_kernel(const float* __restrict__ X, const float* __restrict__ Wf,
             float* __restrict__ Yp, const float* __restrict__ scl,
             const float* __restrict__ shf,
             int B_, int D, int H, int W, int O, int S) {
    constexpr int NCOL = BN / TN;
    constexpr int CPT = C / KC;
    constexpr int TNH = TN / 2;
    constexpr int A4 = BM * KC / 4;
    constexpr int NA = (A4 + THREADS - 1) / THREADS;
    constexpr int B4 = BN * KC / 4;
    constexpr int NB = (B4 + THREADS - 1) / THREADS;
    __shared__ alignas(16) float As[2][KC][BM];
    __shared__ alignas(16) float Bs[2][KC][BN];
    __shared__ int sBase[BM];
    __shared__ int sDHW[BM];
    __shared__ alignas(16) float sScale[BNIN ? C : 4];
    __shared__ alignas(16) float sShift[BNIN ? C : 4];
    const int M = B_ * D * H * W;
    const int m0 = blockIdx.x * BM;
    const int n0 = blockIdx.y * BN;
    const int z = blockIdx.z;
    const int s0 = (27 * z) / S, s1 = (27 * (z + 1)) / S;
    const int nChunks = (s1 - s0) * CPT;
    const int tid = threadIdx.x;
    const int col = tid % NCOL, row = tid / NCOL;
    const int rowBase = row * TM, colBase = col * TN;

    if constexpr (BNIN) {
        for (int i = tid; i < C; i += THREADS) {
            sScale[i] = scl[i];
            sShift[i] = shf[i];
        }
    }
    for (int i = tid; i < BM; i += THREADS) {
        int m = m0 + i;
        if (m < M) {
            int w = m % W;
            int t = m / W;
            int h = t % H;
            t /= H;
            int d = t % D;
            sBase[i] = m * C;
            sDHW[i] = (d << 20) | (h << 10) | w;
        } else {
            sBase[i] = -1;
            sDHW[i] = 0;
        }
    }
    __syncthreads();

    ull_t acc[TM][TNH];
#pragma unroll
    for (int a = 0; a < TM; a++)
#pragma unroll
        for (int b = 0; b < TNH; b++) acc[a][b] = 0ULL;

    float4 stA[NA], stB[NB];
    auto gather = [&](int j) {
        int s = s0 + j / CPT;
        int c0 = (j % CPT) * KC;
        int dz = s / 9 - 1, dy = (s / 3) % 3 - 1, dx = s % 3 - 1;
        int koff = ((dz * H + dy) * W + dx) * C + c0;
#pragma unroll
        for (int t = 0; t < NA; t++) {
            int q = tid + t * THREADS;
            float4 v = make_float4(0.f, 0.f, 0.f, 0.f);
            if (A4 % THREADS == 0 || q < A4) {
                int i = q % BM;
                int cc4 = q / BM;
                int bs = sBase[i];
                if (bs >= 0) {
                    int dhw = sDHW[i];
                    int dd = (dhw >> 20) + dz;
                    int hh = ((dhw >> 10) & 1023) + dy;
                    int ww = (dhw & 1023) + dx;
                    if ((unsigned)dd < (unsigned)D && (unsigned)hh < (unsigned)H &&
                        (unsigned)ww < (unsigned)W) {
                        v = *reinterpret_cast<const float4*>(X + bs + koff + cc4 * 4);
                        if constexpr (BNIN) {
                            int ch = c0 + cc4 * 4;
                            float4 sc = *reinterpret_cast<const float4*>(&sScale[ch]);
                            float4 sh = *reinterpret_cast<const float4*>(&sShift[ch]);
                            v.x = fmaf(v.x, sc.x, sh.x);
                            v.y = fmaf(v.y, sc.y, sh.y);
                            v.z = fmaf(v.z, sc.z, sh.z);
                            v.w = fmaf(v.w, sc.w, sh.w);
                        }
                    }
                }
            }
            stA[t] = v;
        }
        const float* wb = Wf + ((size_t)(s * C + c0)) * O + n0;
#pragma unroll
        for (int t = 0; t < NB; t++) {
            int q = tid + t * THREADS;
            float4 v = make_float4(0.f, 0.f, 0.f, 0.f);
            if (B4 % THREADS == 0 || q < B4) {
                int cc = q / (BN / 4);
                int c4 = q % (BN / 4);
                v = *reinterpret_cast<const float4*>(wb + (size_t)cc * O + c4 * 4);
            }
            stB[t] = v;
        }
    };
    auto commit = [&](int buf) {
#pragma unroll
        for (int t = 0; t < NA; t++) {
            int q = tid + t * THREADS;
            if (A4 % THREADS == 0 || q < A4) {
                int i = q % BM;
                int cc = (q / BM) * 4;
                As[buf][cc + 0][i] = stA[t].x;
                As[buf][cc + 1][i] = stA[t].y;
                As[buf][cc + 2][i] = stA[t].z;
                As[buf][cc + 3][i] = stA[t].w;
            }
        }
#pragma unroll
        for (int t = 0; t < NB; t++) {
            int q = tid + t * THREADS;
            if (B4 % THREADS == 0 || q < B4) {
                int cc = q / (BN / 4);
                int c4 = q % (BN / 4);
                *reinterpret_cast<float4*>(&Bs[buf][cc][c4 * 4]) = stB[t];
            }
        }
    };

    gather(0);
    commit(0);
    __syncthreads();
    int cur = 0;
    for (int j = 0; j < nChunks; ++j) {
        if (j + 1 < nChunks) gather(j + 1);
#pragma unroll
        for (int cc = 0; cc < KC; ++cc) {
            float a[TM];
            *reinterpret_cast<float4*>(&a[0]) = *reinterpret_cast<const float4*>(&As[cur][cc][rowBase]);
            *reinterpret_cast<float4*>(&a[4]) = *reinterpret_cast<const float4*>(&As[cur][cc][rowBase + 4]);
            ull_t bp[TNH];
            if constexpr (TN == 8) {
                ulonglong2 b0 = *reinterpret_cast<const ulonglong2*>(&Bs[cur][cc][colBase]);
                ulonglong2 b1 = *reinterpret_cast<const ulonglong2*>(&Bs[cur][cc][colBase + 4]);
                bp[0] = b0.x; bp[1] = b0.y; bp[2] = b1.x; bp[3] = b1.y;
            } else {
                const ull_t* pb = reinterpret_cast<const ull_t*>(&Bs[cur][cc][colBase]);
#pragma unroll
                for (int p = 0; p < TNH; p++) bp[p] = pb[p];
            }
#pragma unroll
            for (int mm = 0; mm < TM; mm++) {
                ull_t ap;
                PACK2(ap, a[mm]);
#pragma unroll
                for (int p = 0; p < TNH; p++) FMA2(acc[mm][p], ap, bp[p]);
            }
        }
        if (j + 1 < nChunks) commit(cur ^ 1);
        __syncthreads();
        cur ^= 1;
    }

    float* out = Yp + (size_t)z * M * O;
#pragma unroll
    for (int mm = 0; mm < TM; mm++) {
        int m = m0 + rowBase + mm;
        if (m < M) {
            ull_t* dst = reinterpret_cast<ull_t*>(out + (size_t)m * O + n0 + colBase);
#pragma unroll
            for (int p = 0; p < TNH; p++) dst[p] = acc[mm][p];
        }
    }
}

// ------ split-K reduce + clamp(1+x,0) + maxpool (1,2,2) + sum/sumsq ----------
// v3: channel-major thread mapping (o = g % O fixed; NT % O == 0) with
// CONTIGUOUS per-thread spatial chunks + carry counters: ONE div/mod chain at
// loop entry, then wp++ with carry — no per-iteration integer division.
// Stats in 2 registers; 2 shared atomics per thread. Coalescing unchanged
// (threads in a chunk group span adjacent channels at the same pixel).
__global__ void pool_stats_kernel(const float* __restrict__ Y, float* __restrict__ P,
                                  float* __restrict__ gsum, float* __restrict__ gsq,
                                  int B, int D, int H, int W, int O, int Hp, int Wp,
                                  int S, int sliceStride) {
    __shared__ float ssum[384];
    __shared__ float ssq[384];
    int tid = threadIdx.x;
    for (int o = tid; o < O; o += blockDim.x) { ssum[o] = 0.f; ssq[o] = 0.f; }
    __syncthreads();
    const int NT = gridDim.x * blockDim.x;     // launch guarantees NT % O == 0
    const int g = blockIdx.x * blockDim.x + tid;
    const int o = g % O;                       // constant across the loop
    const int chunk = g / O;
    const int nChunks = NT / O;
    const int NSP = B * D * Hp * Wp;
    const int cs = (NSP + nChunks - 1) / nChunks;
    int sp = chunk * cs;
    int spEnd = sp + cs;
    if (spEnd > NSP) spEnd = NSP;
    float rs = 0.f, rq = 0.f;
    if (sp < spEnd) {
        // decompose once
        int wp = sp % Wp;
        int t = sp / Wp;
        int hp = t % Hp;
        t /= Hp;
        int d = t % D;
        int b = t / D;
        const size_t rowW = (size_t)W * O;
        for (; sp < spEnd; ++sp) {
            size_t off = ((size_t)(((b * D + d) * H + hp * 2) * W) + wp * 2) * O + o;
            float v0 = 0.f, v1 = 0.f, v2 = 0.f, v3 = 0.f;
            for (int s = 0; s < S; s++) {
                const float* src = Y + off + (size_t)s * sliceStride;
                v0 += src[0];
                v1 += src[O];
                v2 += src[rowW];
                v3 += src[rowW + O];
            }
            float v = fmaxf(fmaxf(v0, v1), fmaxf(v2, v3));
            v = fmaxf(1.f + v, 0.f);
            P[(size_t)sp * O + o] = v;
            rs += v;
            rq += v * v;
            // carry counters (no division)
            if (++wp == Wp) {
                wp = 0;
                if (++hp == Hp) {
                    hp = 0;
                    if (++d == D) { d = 0; ++b; }
                }
            }
        }
    }
    atomicAdd(&ssum[o], rs);
    atomicAdd(&ssq[o], rq);
    __syncthreads();
    for (int oo = tid; oo < O; oo += blockDim.x) {
        atomicAdd(&gsum[oo], ssum[oo]);
        atomicAdd(&gsq[oo], ssq[oo]);
    }
}

// Computes scale/shift, then RE-ZEROES the stat buffers for the next layer
// (stream-ordered before the next pool; deterministic across graph replays).
__global__ void bn_final_kernel(float* __restrict__ sum, float* __restrict__ sq,
                                const float* __restrict__ gamma, const float* __restrict__ beta,
                                float* __restrict__ scale, float* __restrict__ shift,
                                float invN, int O) {
    int o = threadIdx.x;
    if (o < O) {
        float mean = sum[o] * invN;
        float var = sq[o] * invN - mean * mean;
        float sc = gamma[o] * rsqrtf(var + 1e-5f);
        scale[o] = sc;
        shift[o] = beta[o] - mean * sc;
    }
    if (o < 384) { sum[o] = 0.f; sq[o] = 0.f; }
}

// ---------------- FC layers --------------------------------------------------
// v: pooled L5 (pre-BN); BN affine applied inline here.
__global__ void fc1_kernel(const float* __restrict__ v, const float* __restrict__ w1,
                           const float* __restrict__ b1,
                           const float* __restrict__ scale, const float* __restrict__ shift,
                           float* __restrict__ out) {
    __shared__ float s0[256];
    __shared__ float s1[256];
    __shared__ float sSc[384];
    __shared__ float sSh[384];
    int j = blockIdx.x;
    int tid = threadIdx.x;
    for (int o = tid; o < 384; o += 256) { sSc[o] = scale[o]; sSh[o] = shift[o]; }
    __syncthreads();
    const float* wr = w1 + (size_t)j * 55296;
    float a0 = 0.f, a1 = 0.f;
    for (int k = tid; k < 55296; k += 256) {
        int o = k / 144;
        int r = k - o * 144;
        int idx = r * 384 + o;
        float sc = sSc[o], sh = sSh[o];
        float wv = wr[k];
        a0 += wv * fmaf(v[idx], sc, sh);
        a1 += wv * fmaf(v[idx + 55296], sc, sh);
    }
    s0[tid] = a0; s1[tid] = a1;
    __syncthreads();
    for (int t = 128; t > 0; t >>= 1) {
        if (tid < t) { s0[tid] += s0[tid + t]; s1[tid] += s1[tid + t]; }
        __syncthreads();
    }
    if (tid == 0) {
        out[j] = fmaxf(s0[0] + b1[j], 0.f);
        out[512 + j] = fmaxf(s1[0] + b1[j], 0.f);
    }
}

__global__ void fc2_kernel(const float* __restrict__ in, const float* __restrict__ w2,
                           const float* __restrict__ b2, float* __restrict__ out) {
    __shared__ float s0[128];
    __shared__ float s1[128];
    int i = blockIdx.x;
    int tid = threadIdx.x;
    float a0 = 0.f, a1 = 0.f;
    for (int j = tid; j < 512; j += 128) {
        float wv = w2[i * 512 + j];
        a0 += wv * in[j];
        a1 += wv * in[512 + j];
    }
    s0[tid] = a0; s1[tid] = a1;
    __syncthreads();
    for (int t = 64; t > 0; t >>= 1) {
        if (tid < t) { s0[tid] += s0[tid + t]; s1[tid] += s1[tid + t]; }
        __syncthreads();
    }
    if (tid == 0) {
        out[i] = fmaxf(s0[0] + b2[i], 0.f);
        out[256 + i] = fmaxf(s1[0] + b2[i], 0.f);
    }
}

__global__ void fc3_kernel(const float* __restrict__ in, const float* __restrict__ w3,
                           const float* __restrict__ b3, float* __restrict__ out) {
    __shared__ float s0[128];
    __shared__ float s1[128];
    int i = blockIdx.x;
    int tid = threadIdx.x;
    float a0 = 0.f, a1 = 0.f;
    for (int j = tid; j < 256; j += 128) {
        float wv = w3[i * 256 + j];
        a0 += wv * in[j];
        a1 += wv * in[256 + j];
    }
    s0[tid] = a0; s1[tid] = a1;
    __syncthreads();
    for (int t = 64; t > 0; t >>= 1) {
        if (tid < t) { s0[tid] += s0[tid + t]; s1[tid] += s1[tid + t]; }
        __syncthreads();
    }
    if (tid == 0) {
        out[i] = s0[0] + b3[i];
        out[101 + i] = s1[0] + b3[i];
    }
}

// ---------------- driver ------------------------------------------------------
extern "C" void kernel_launch(void* const* d_in, const int* in_sizes, int n_in,
                              void* d_out, int out_size) {
    const float* x = (const float*)d_in[0];
    const float* Pj[5];
    const float* Al[5];
    const float* Ga[5];
    const float* Be[5];
    for (int i = 0; i < 5; i++) {
        Pj[i] = (const float*)d_in[1 + 4 * i];
        Al[i] = (const float*)d_in[2 + 4 * i];
        Ga[i] = (const float*)d_in[3 + 4 * i];
        Be[i] = (const float*)d_in[4 + 4 * i];
    }
    const float* w1 = (const float*)d_in[21];
    const float* b1 = (const float*)d_in[22];
    const float* w2 = (const float*)d_in[23];
    const float* b2 = (const float*)d_in[24];
    const float* w3 = (const float*)d_in[25];
    const float* b3 = (const float*)d_in[26];

    float *preact, *act, *wf, *sum, *sq, *scale, *shift, *fc1b, *fc2b;
    cudaGetSymbolAddress((void**)&preact, g_preact);
    cudaGetSymbolAddress((void**)&act, g_act);
    cudaGetSymbolAddress((void**)&wf, g_wf);
    cudaGetSymbolAddress((void**)&sum, g_sum);
    cudaGetSymbolAddress((void**)&sq, g_sumsq);
    cudaGetSymbolAddress((void**)&scale, g_scale);
    cudaGetSymbolAddress((void**)&shift, g_shift);
    cudaGetSymbolAddress((void**)&fc1b, g_fc1);
    cudaGetSymbolAddress((void**)&fc2b, g_fc2);

    // input transpose to channel-last (+ upfront stats zero)
    {
        int N = 2 * 3 * 16 * 112 * 112;
        nchw2nhwc_kernel<<<(N + 255) / 256, 256>>>(x, act, sum, sq);
    }

    const int B = 2, D = 16;

    auto do_pool_bn = [&](int C_H, int C_W, int C_O, int C_S, int C_M,
                          const float* gamma, const float* beta) {
        int hp = (C_H - 2) / 2 + 1;
        int wp = (C_W - 2) / 2 + 1;
        int ne = B * D * hp * wp * C_O;
        // blocks multiple of 3 (256*3=768 divisible by all O) -> NT % O == 0;
        // sized for ~4-8 spatial elements per thread, capped at 1536.
        int pb = (ne / 256 + 23) / 24 * 3;
        if (pb < 3) pb = 3;
        if (pb > 1536) pb = 1536;
        pool_stats_kernel<<<pb, 256>>>(preact, act, sum, sq, B, D, C_H, C_W, C_O, hp, wp,
                                       C_S, C_M * C_O);
        float invN = 1.f / (float)(B * D * hp * wp);
        bn_final_kernel<<<1, 384>>>(sum, sq, gamma, beta, scale, shift, invN, C_O);
    };

    // ---------------- layer 1: C=3, O=24, H=W=112 (no BN on input) ----------
    fusew_kernel<32, 2><<<dim3(2, 1), 256>>>(Pj[0], Al[0], wf, 81, 3, 24);
    conv1_kernel<<<1568, 256>>>(act, wf, preact);
    do_pool_bn(112, 112, 24, 1, 2 * 16 * 112 * 112, Ga[0], Be[0]);

    // ---------------- layer 2: C=24, O=48, H=W=56 ---------------------------
    fusew_kernel<64, 4><<<dim3((648 + 63) / 64, 1), 256>>>(Pj[1], Al[1], wf, 648, 24, 48);
    int M = 2 * 16 * 56 * 56;
    conv2_kernel<128, 48, 8, 6, 8, 24, 128, true>
        <<<dim3(M / 128, 1, 1), 128>>>(act, wf, preact, scale, shift, B, D, 56, 56, 48, 1);
    do_pool_bn(56, 56, 48, 1, M, Ga[1], Be[1]);

    // ---------------- layer 3: C=48, O=96, H=W=28, split-K=3 ----------------
    fusew2_kernel<128, 96, 8, 8, 16, 192, 2>
        <<<dim3(11, 1), 192>>>(Pj[2], Al[2], wf, 1296, 48, 96);
    M = 2 * 16 * 28 * 28;
    conv2_kernel<128, 96, 8, 8, 16, 48, 192, true>
        <<<dim3(M / 128, 1, 3), 192>>>(act, wf, preact, scale, shift, B, D, 28, 28, 96, 3);
    do_pool_bn(28, 28, 96, 3, M, Ga[2], Be[2]);

    // ---------------- layer 4: C=96, O=192, H=W=14, split-K=3 ---------------
    fusew2_kernel<128, 96, 8, 8, 16, 192, 2>
        <<<dim3(21, 2), 192>>>(Pj[3], Al[3], wf, 2592, 96, 192);
    M = 2 * 16 * 14 * 14;
    conv2_kernel<128, 96, 8, 8, 16, 96, 192, true>
        <<<dim3(M / 128, 2, 3), 192>>>(act, wf, preact, scale, shift, B, D, 14, 14, 192, 3);
    do_pool_bn(14, 14, 192, 3, M, Ga[3], Be[3]);

    // ---------------- layer 5: C=192, O=384, H=W=7, split-K=4 ---------------
    fusew2_kernel<128, 128, 8, 8, 16, 256, 1>
        <<<dim3(41, 3), 256>>>(Pj[4], Al[4], wf, 5184, 192, 384);
    M = 2 * 16 * 7 * 7;
    conv2_kernel<64, 128, 8, 8, 16, 192, 128, true>
        <<<dim3((M + 63) / 64, 3, 4), 128>>>(act, wf, preact, scale, shift, B, D, 7, 7, 384, 4);
    do_pool_bn(7, 7, 384, 4, M, Ga[4], Be[4]);

    // ---------------- FC head (L5 BN fused into FC1 input) ------------------
    fc1_kernel<<<512, 256>>>(act, w1, b1, scale, shift, fc1b);
    fc2_kernel<<<256, 128>>>(fc1b, w2, b2, fc2b);
    fc3_kernel<<<101, 128>>>(fc2b, w3, b3, (float*)d_out);
}